// round 8
// baseline (speedup 1.0000x reference)
#include <cuda_runtime.h>

#define NN 100000
#define EE 800000
#define SCAN_CHUNK 1024
#define SCAN_NB 98   // 98*1024 = 100352 >= NN

typedef unsigned long long ull;

// ---------------- scratch (device globals) ----------------
__device__ float g_h1[NN * 64];
__device__ float g_h2[NN * 64];
__device__ float g_z[NN * 128];
__device__ float g_asrc[NN * 2];
__device__ float g_adst[NN * 2];
__device__ float g_Wn2[3][4096];   // rearranged: [(k*32+c)*2 + half] = Wn[k][c + 32*half]
__device__ float g_We[3][320];
__device__ float g_bp[3][64];
__device__ float g_Wstk[8192];     // [k][c] k<64: Wg[k][c]; k>=64: Wg[k-64][64+c]
__device__ float g_avec[256];      // avS0[64], avS1[64], avD0[64], avD1[64]
__device__ int g_cnt[NN];
__device__ int g_rowptr[NN + 4];
__device__ int g_csr_src[EE];
__device__ float g_S[NN * 5];
__device__ int g_bsum[SCAN_NB];
__device__ int g_boff[SCAN_NB];

__device__ __forceinline__ float lrelu(float x) { return x > 0.f ? x : 0.2f * x; }

// f32x2 packed math
__device__ __forceinline__ ull pk2(float x) {
    ull r; asm("mov.b64 %0,{%1,%1};" : "=l"(r) : "f"(x)); return r;
}
__device__ __forceinline__ void fma2(ull& d, ull a, ull b) {
    asm("fma.rn.f32x2 %0,%1,%2,%0;" : "+l"(d) : "l"(a), "l"(b));
}
__device__ __forceinline__ float2 up2(ull v) {
    float2 r; asm("mov.b64 {%0,%1},%2;" : "=f"(r.x), "=f"(r.y) : "l"(v)); return r;
}

// ---------------- weight folding ----------------
// y<3: layer L -> Wn2 (rearranged), We', bp'
// y==3: Wstk (Wg stacked per head) + avec (Wg @ att vectors)
struct FoldW { const float* w[18]; const float* wg; const float* as; const float* ad; };

__global__ void fold_kernel(FoldW fw, float* __restrict__ Wn2, float* __restrict__ We,
                            float* __restrict__ bp, float* __restrict__ Wstk,
                            float* __restrict__ avec) {
    int L = blockIdx.y;
    int t = blockIdx.x * 256 + threadIdx.x;
    if (L < 3) {
        if (t >= 4480) return;
        const float* wn = fw.w[6 * L + 0];
        const float* bn = fw.w[6 * L + 1];
        const float* we = fw.w[6 * L + 2];
        const float* be = fw.w[6 * L + 3];
        const float* wc = fw.w[6 * L + 4];
        const float* bc = fw.w[6 * L + 5];
        if (t < 4096) {
            int r = t >> 6, c = t & 63;
            float s = 0.f;
            #pragma unroll 8
            for (int k = 0; k < 64; k++) s += wn[r * 64 + k] * wc[k * 64 + c];
            // rearranged store: pair (c mod 32, half c/32)
            Wn2[L * 4096 + (r * 32 + (c & 31)) * 2 + (c >> 5)] = s;
        } else if (t < 4416) {
            int u = t - 4096;
            int j = u >> 6, c = u & 63;
            float s = 0.f;
            #pragma unroll 8
            for (int k = 0; k < 64; k++) s += we[j * 64 + k] * wc[(64 + k) * 64 + c];
            We[L * 320 + u] = s;
        } else {
            int c = t - 4416;
            float s = bc[c];
            #pragma unroll 8
            for (int k = 0; k < 64; k++)
                s += bn[k] * wc[k * 64 + c] + be[k] * wc[(64 + k) * 64 + c];
            bp[L * 64 + c] = s;
        }
    } else {
        if (t < 8192) {
            int k = t >> 6, c = t & 63;
            Wstk[t] = (k < 64) ? fw.wg[k * 128 + c] : fw.wg[(k - 64) * 128 + 64 + c];
        } else if (t < 8448) {
            int u = t - 8192;          // 0..255
            int vec = u >> 6;          // 0:avS0 1:avS1 2:avD0 3:avD1
            int k = u & 63;
            int hd = vec & 1;
            const float* att = (vec < 2) ? fw.as : fw.ad;
            float s = 0.f;
            #pragma unroll 8
            for (int c = 0; c < 64; c++) s += fw.wg[k * 128 + hd * 64 + c] * att[hd * 64 + c];
            avec[u] = s;
        }
    }
}

// ---------------- zero fill ----------------
__global__ void zero4_kernel(float4* __restrict__ p, int n4) {
    float4 z = make_float4(0.f, 0.f, 0.f, 0.f);
    for (int i = blockIdx.x * blockDim.x + threadIdx.x; i < n4; i += gridDim.x * blockDim.x)
        p[i] = z;
}

// ---------------- CSR build ----------------
__global__ void count_kernel(const int* __restrict__ dst, int* __restrict__ cnt) {
    int i = blockIdx.x * blockDim.x + threadIdx.x;
    if (i * 4 >= EE) return;
    int4 d = ((const int4*)dst)[i];
    atomicAdd(&cnt[d.x], 1);
    atomicAdd(&cnt[d.y], 1);
    atomicAdd(&cnt[d.z], 1);
    atomicAdd(&cnt[d.w], 1);
}

__global__ void scan_part(const int* __restrict__ cnt, int* __restrict__ bsum) {
    __shared__ int wsum[8];
    int b = blockIdx.x, t = threadIdx.x;
    int lane = t & 31, wid = t >> 5;
    int idx = b * SCAN_CHUNK + t * 4;
    int s = 0;
    if (idx < NN) {
        int4 v = *(const int4*)(cnt + idx);
        s = v.x + v.y + v.z + v.w;
    }
    #pragma unroll
    for (int o = 16; o; o >>= 1) s += __shfl_xor_sync(0xffffffffu, s, o);
    if (lane == 0) wsum[wid] = s;
    __syncthreads();
    if (t == 0) {
        int tot = 0;
        #pragma unroll
        for (int w = 0; w < 8; w++) tot += wsum[w];
        bsum[b] = tot;
    }
}

__global__ void scan_top(const int* __restrict__ bsum, int* __restrict__ boff) {
    __shared__ int wtot[4];
    int t = threadIdx.x;           // 128 threads
    int lane = t & 31, wid = t >> 5;
    int v = (t < SCAN_NB) ? bsum[t] : 0;
    int incl = v;
    #pragma unroll
    for (int o = 1; o < 32; o <<= 1) {
        int u = __shfl_up_sync(0xffffffffu, incl, o);
        if (lane >= o) incl += u;
    }
    if (lane == 31) wtot[wid] = incl;
    __syncthreads();
    int woff = 0;
    for (int w = 0; w < wid; w++) woff += wtot[w];
    if (t < SCAN_NB) boff[t] = woff + incl - v;
}

__global__ void scan_final(const int* __restrict__ cnt, const int* __restrict__ boff,
                           int* __restrict__ rowptr) {
    __shared__ int wsum[8];
    int b = blockIdx.x, t = threadIdx.x;
    int lane = t & 31, wid = t >> 5;
    int idx = b * SCAN_CHUNK + t * 4;
    int v[4] = {0, 0, 0, 0};
    if (idx < NN) {
        int4 d = *(const int4*)(cnt + idx);
        v[0] = d.x; v[1] = d.y; v[2] = d.z; v[3] = d.w;
    }
    #pragma unroll
    for (int j = 1; j < 4; j++) v[j] += v[j - 1];
    int tot = v[3];
    int incl = tot;
    #pragma unroll
    for (int o = 1; o < 32; o <<= 1) {
        int u = __shfl_up_sync(0xffffffffu, incl, o);
        if (lane >= o) incl += u;
    }
    if (lane == 31) wsum[wid] = incl;
    __syncthreads();
    int woff = 0;
    for (int w = 0; w < wid; w++) woff += wsum[w];
    int excl = boff[b] + woff + incl - tot;
    if (idx < NN) {
        #pragma unroll
        for (int j = 0; j < 4; j++) rowptr[idx + j + 1] = excl + v[j];
    }
    if (b == 0 && t == 0) rowptr[0] = 0;
}

__device__ __forceinline__ void scat1(int d, int s, int e, const int* __restrict__ rowptr,
                                      int* __restrict__ cnt, int* __restrict__ csr_src,
                                      const float* __restrict__ ea, float* __restrict__ S) {
    int pos = atomicAdd(&cnt[d], -1) - 1;
    csr_src[rowptr[d] + pos] = s;
    const float* eap = ea + (size_t)e * 5;
    #pragma unroll
    for (int k = 0; k < 5; k++) atomicAdd(&S[d * 5 + k], eap[k]);
}

__global__ void scatter_kernel(const int* __restrict__ src, const int* __restrict__ dst,
                               const int* __restrict__ rowptr, int* __restrict__ cnt,
                               int* __restrict__ csr_src, const float* __restrict__ ea,
                               float* __restrict__ S) {
    int i = blockIdx.x * blockDim.x + threadIdx.x;
    if (i * 4 >= EE) return;
    int4 d4 = ((const int4*)dst)[i];
    int4 s4 = ((const int4*)src)[i];
    int e = i * 4;
    scat1(d4.x, s4.x, e + 0, rowptr, cnt, csr_src, ea, S);
    scat1(d4.y, s4.y, e + 1, rowptr, cnt, csr_src, ea, S);
    scat1(d4.z, s4.z, e + 2, rowptr, cnt, csr_src, ea, S);
    scat1(d4.w, s4.w, e + 3, rowptr, cnt, csr_src, ea, S);
}

// ---------------- fused layer: gather-sum + in-register matvec (+ attn epilogue) ----------------
// out[n] = relu( (Σ_src hin[src]) @ Wn' + S[n]@We' + deg*b' )   [stored relu'd]
// attn: also asrc/adst[n][hd] = out[n] . avec
__global__ __launch_bounds__(256) void aggemm_kernel(
    const float* __restrict__ hin, const int* __restrict__ csr_src,
    const int* __restrict__ rowptr, const float* __restrict__ S,
    const float* __restrict__ Wn2, const float* __restrict__ We,
    const float* __restrict__ bp, float* __restrict__ out,
    int attn, const float* __restrict__ avec,
    float* __restrict__ aS, float* __restrict__ aD) {
    __shared__ float2 sW2[64 * 32];   // 16KB: sW2[k*32+c] = (Wn[k][c], Wn[k][c+32])
    __shared__ float sWe[320];
    __shared__ float sbp[64];
    __shared__ float sAv[256];
    int t = threadIdx.x;
    #pragma unroll
    for (int i = 0; i < 4; i++) {
        int idx = t + i * 256;      // 0..1023 float2
        sW2[idx * 2] = ((const float2*)Wn2)[idx * 2];
        sW2[idx * 2 + 1] = ((const float2*)Wn2)[idx * 2 + 1];
    }
    for (int i = t; i < 384; i += 256) {
        if (i < 320) sWe[i] = We[i];
        else sbp[i - 320] = bp[i - 320];
    }
    if (attn && t < 256) sAv[t] = avec[t];
    __syncthreads();

    int n = blockIdx.x * 8 + (t >> 5);
    int lane = t & 31;
    int start = rowptr[n], end = rowptr[n + 1];

    // gather-sum
    float q0 = 0.f, q1 = 0.f;
    int j = start;
    for (; j + 1 < end; j += 2) {
        int sa = csr_src[j], sb = csr_src[j + 1];
        const float* pa = hin + (size_t)sa * 64;
        const float* pb = hin + (size_t)sb * 64;
        q0 += pa[lane] + pb[lane];
        q1 += pa[lane + 32] + pb[lane + 32];
    }
    if (j < end) {
        const float* pa = hin + (size_t)csr_src[j] * 64;
        q0 += pa[lane];
        q1 += pa[lane + 32];
    }

    // edge-attr + bias part
    float s0 = S[n * 5 + 0], s1 = S[n * 5 + 1], s2 = S[n * 5 + 2],
          s3 = S[n * 5 + 3], s4 = S[n * 5 + 4];
    float deg = (float)(end - start);
    int c = lane, c2 = lane + 32;
    float acc0 = deg * sbp[c] + s0 * sWe[c] + s1 * sWe[64 + c] + s2 * sWe[128 + c] +
                 s3 * sWe[192 + c] + s4 * sWe[256 + c];
    float acc1 = deg * sbp[c2] + s0 * sWe[c2] + s1 * sWe[64 + c2] + s2 * sWe[128 + c2] +
                 s3 * sWe[192 + c2] + s4 * sWe[256 + c2];

    // matvec q @ Wn' via shfl broadcast
    #pragma unroll
    for (int k = 0; k < 32; k++) {
        float qk = __shfl_sync(0xffffffffu, q0, k);
        float2 w = sW2[k * 32 + lane];
        acc0 += qk * w.x;
        acc1 += qk * w.y;
    }
    #pragma unroll
    for (int k = 0; k < 32; k++) {
        float qk = __shfl_sync(0xffffffffu, q1, k);
        float2 w = sW2[(k + 32) * 32 + lane];
        acc0 += qk * w.x;
        acc1 += qk * w.y;
    }

    float r0 = fmaxf(acc0, 0.f);
    float r1 = fmaxf(acc1, 0.f);
    out[(size_t)n * 64 + c] = r0;
    out[(size_t)n * 64 + c2] = r1;

    if (attn) {
        float vS0 = r0 * sAv[lane] + r1 * sAv[lane + 32];
        float vS1 = r0 * sAv[64 + lane] + r1 * sAv[96 + lane];
        float vD0 = r0 * sAv[128 + lane] + r1 * sAv[160 + lane];
        float vD1 = r0 * sAv[192 + lane] + r1 * sAv[224 + lane];
        #pragma unroll
        for (int o = 16; o; o >>= 1) {
            vS0 += __shfl_xor_sync(0xffffffffu, vS0, o);
            vS1 += __shfl_xor_sync(0xffffffffu, vS1, o);
            vD0 += __shfl_xor_sync(0xffffffffu, vD0, o);
            vD1 += __shfl_xor_sync(0xffffffffu, vD1, o);
        }
        if (lane == 0) {
            aS[n * 2] = vS0; aS[n * 2 + 1] = vS1;
            aD[n * 2] = vD0; aD[n * 2 + 1] = vD1;
        }
    }
}

// ---------------- GAT aggregation: softmax-weighted sum of r rows -> z[N,128] ----------------
__global__ void gat_agg_kernel(const int* __restrict__ csr_src, const int* __restrict__ rowptr,
                               const float2* __restrict__ aS, const float2* __restrict__ aD,
                               const float* __restrict__ r, float* __restrict__ z) {
    int n = blockIdx.x * 8 + (threadIdx.x >> 5);
    int lane = threadIdx.x & 31;
    int start = rowptr[n], end = rowptr[n + 1];
    float2 ad = aD[n];
    float m0 = -1e30f, m1 = -1e30f;
    for (int j = start; j < end; j++) {
        float2 as = aS[csr_src[j]];
        m0 = fmaxf(m0, lrelu(as.x + ad.x));
        m1 = fmaxf(m1, lrelu(as.y + ad.y));
    }
    float acc0 = 0.f, acc1 = 0.f, acc2 = 0.f, acc3 = 0.f, den0 = 0.f, den1 = 0.f;
    for (int j = start; j < end; j++) {
        int s = csr_src[j];
        float2 as = aS[s];
        float w0 = __expf(lrelu(as.x + ad.x) - m0);
        float w1 = __expf(lrelu(as.y + ad.y) - m1);
        den0 += w0;
        den1 += w1;
        const float* rs = r + (size_t)s * 64;
        float v0 = rs[lane], v1 = rs[lane + 32];
        acc0 += w0 * v0;
        acc1 += w0 * v1;
        acc2 += w1 * v0;
        acc3 += w1 * v1;
    }
    float id0 = 0.5f / (den0 + 1e-16f);
    float id1 = 0.5f / (den1 + 1e-16f);
    float* zn = z + (size_t)n * 128;
    zn[lane]      = acc0 * id0;
    zn[lane + 32] = acc1 * id0;
    zn[lane + 64] = acc2 * id1;
    zn[lane + 96] = acc3 * id1;
}

// ---------------- final GEMM: out = z[N,128] @ Wstk[128,64] + b_gat ----------------
__global__ __launch_bounds__(256) void gemm_fin(
    const float* __restrict__ z, const float* __restrict__ Wstk,
    const float* __restrict__ bias, float* __restrict__ out, int n) {
    __shared__ float Ws[128][64];   // 32KB
    int n0 = blockIdx.x << 8;
    int t = threadIdx.x;
    int tx = t & 7, ty = t >> 3;

    #pragma unroll
    for (int i = 0; i < 8; i++) {
        int idx = t + i * 256;
        int k = idx >> 4;
        int c4 = (idx & 15) << 2;
        *(float4*)&Ws[k][c4] = *(const float4*)(Wstk + k * 64 + c4);
    }
    __syncthreads();

    int r0 = n0 + ty * 8;
    ull acc[8][4];
    #pragma unroll
    for (int i = 0; i < 8; i++)
        #pragma unroll
        for (int j = 0; j < 4; j++) acc[i][j] = 0ull;

    for (int kc = 0; kc < 128; kc += 4) {
        float4 a[8];
        #pragma unroll
        for (int i = 0; i < 8; i++) {
            int row = r0 + i;
            a[i] = (row < n) ? *(const float4*)(z + (size_t)row * 128 + kc)
                             : make_float4(0.f, 0.f, 0.f, 0.f);
        }
        #pragma unroll
        for (int kk = 0; kk < 4; kk++) {
            const ull* bb = (const ull*)&Ws[kc + kk][tx * 8];
            ull b0 = bb[0], b1 = bb[1], b2 = bb[2], b3 = bb[3];
            #pragma unroll
            for (int i = 0; i < 8; i++) {
                float av = (kk == 0) ? a[i].x : (kk == 1) ? a[i].y : (kk == 2) ? a[i].z : a[i].w;
                ull a2 = pk2(av);
                fma2(acc[i][0], a2, b0);
                fma2(acc[i][1], a2, b1);
                fma2(acc[i][2], a2, b2);
                fma2(acc[i][3], a2, b3);
            }
        }
    }

    float4 bA = *(const float4*)(bias + tx * 8);
    float4 bB = *(const float4*)(bias + tx * 8 + 4);
    #pragma unroll
    for (int i = 0; i < 8; i++) {
        int row = r0 + i;
        if (row < n) {
            float2 p0 = up2(acc[i][0]), p1 = up2(acc[i][1]);
            float2 p2 = up2(acc[i][2]), p3 = up2(acc[i][3]);
            *(float4*)(out + (size_t)row * 64 + tx * 8) =
                make_float4(p0.x + bA.x, p0.y + bA.y, p1.x + bA.z, p1.y + bA.w);
            *(float4*)(out + (size_t)row * 64 + tx * 8 + 4) =
                make_float4(p2.x + bB.x, p2.y + bB.y, p3.x + bB.z, p3.y + bB.w);
        }
    }
}

// ---------------- launch ----------------
extern "C" void kernel_launch(void* const* d_in, const int* in_sizes, int n_in,
                              void* d_out, int out_size) {
    const float* x = (const float*)d_in[0];
    const int* ei = (const int*)d_in[1];
    const float* ea = (const float*)d_in[2];
    const int* src = ei;
    const int* dst = ei + EE;
    FoldW fw;
    for (int i = 0; i < 18; i++) fw.w[i] = (const float*)d_in[3 + i];
    fw.wg = (const float*)d_in[21];
    fw.as = (const float*)d_in[22];
    fw.ad = (const float*)d_in[23];
    const float* b_gat = (const float*)d_in[24];
    float* out = (float*)d_out;

    float *h1, *h2, *z, *asrc, *adst, *Wn2, *We, *bp, *Wstk, *avec, *S;
    int *cnt, *rowptr, *csr_src, *bsum, *boff;
    cudaGetSymbolAddress((void**)&h1, g_h1);
    cudaGetSymbolAddress((void**)&h2, g_h2);
    cudaGetSymbolAddress((void**)&z, g_z);
    cudaGetSymbolAddress((void**)&asrc, g_asrc);
    cudaGetSymbolAddress((void**)&adst, g_adst);
    cudaGetSymbolAddress((void**)&Wn2, g_Wn2);
    cudaGetSymbolAddress((void**)&We, g_We);
    cudaGetSymbolAddress((void**)&bp, g_bp);
    cudaGetSymbolAddress((void**)&Wstk, g_Wstk);
    cudaGetSymbolAddress((void**)&avec, g_avec);
    cudaGetSymbolAddress((void**)&cnt, g_cnt);
    cudaGetSymbolAddress((void**)&rowptr, g_rowptr);
    cudaGetSymbolAddress((void**)&csr_src, g_csr_src);
    cudaGetSymbolAddress((void**)&S, g_S);
    cudaGetSymbolAddress((void**)&bsum, g_bsum);
    cudaGetSymbolAddress((void**)&boff, g_boff);

    const int NB = NN / 8;                 // 12500 warp-per-node blocks

    // ---- CSR build + weight folding ----
    zero4_kernel<<<98, 256>>>((float4*)cnt, NN / 4);
    count_kernel<<<(EE / 4 + 255) / 256, 256>>>(dst, cnt);
    scan_part<<<SCAN_NB, 256>>>(cnt, bsum);
    scan_top<<<1, 128>>>(bsum, boff);
    fold_kernel<<<dim3(33, 4), 256>>>(fw, Wn2, We, bp, Wstk, avec);
    scan_final<<<SCAN_NB, 256>>>(cnt, boff, rowptr);
    zero4_kernel<<<489, 256>>>((float4*)S, NN * 5 / 4);
    scatter_kernel<<<(EE / 4 + 255) / 256, 256>>>(src, dst, rowptr, cnt, csr_src, ea, S);

    // ---- 3 fused layers (gather + matvec), outputs stored relu'd ----
    aggemm_kernel<<<NB, 256>>>(x, csr_src, rowptr, S, Wn2 + 0 * 4096, We + 0 * 320,
                               bp + 0 * 64, h1, 0, nullptr, nullptr, nullptr);
    aggemm_kernel<<<NB, 256>>>(h1, csr_src, rowptr, S, Wn2 + 1 * 4096, We + 1 * 320,
                               bp + 1 * 64, h2, 0, nullptr, nullptr, nullptr);
    aggemm_kernel<<<NB, 256>>>(h2, csr_src, rowptr, S, Wn2 + 2 * 4096, We + 2 * 320,
                               bp + 2 * 64, h1, 1, avec, asrc, adst);

    // ---- GAT: weighted aggregation then projection ----
    gat_agg_kernel<<<NB, 256>>>(csr_src, rowptr, (const float2*)asrc, (const float2*)adst,
                                h1, z);
    gemm_fin<<<(NN + 255) / 256, 256>>>(z, Wstk, b_gat, out, NN);
}

// round 9
// speedup vs baseline: 1.3817x; 1.3817x over previous
#include <cuda_runtime.h>

#define NN 100000
#define EE 800000
#define SCAN_CHUNK 1024
#define SCAN_NB 98   // 98*1024 = 100352 >= NN

typedef unsigned long long ull;

// ---------------- scratch (device globals) ----------------
__device__ float g_h1[NN * 64];
__device__ float g_h2[NN * 64];
__device__ float g_p[NN * 64];
__device__ float g_z[NN * 128];
__device__ float g_asrc[NN * 2];
__device__ float g_adst[NN * 2];
__device__ float g_Wn[3][4096];
__device__ float g_We[3][320];
__device__ float g_bp[3][64];
__device__ float g_Wstk[8192];     // [k][c]: k<64 -> Wg[k][c] ; k>=64 -> Wg[k-64][64+c]
__device__ float g_avec[256];      // avS0[64] avS1[64] avD0[64] avD1[64]  (Wg @ att vectors)
__device__ int g_cnt[NN];
__device__ int g_rowptr[NN + 4];
__device__ int g_csr_src[EE];
__device__ float g_S[NN * 5];
__device__ int g_bsum[SCAN_NB];
__device__ int g_boff[SCAN_NB];

__device__ __forceinline__ float lrelu(float x) { return x > 0.f ? x : 0.2f * x; }

// f32x2 packed math (Blackwell): 2 fp32 FMAs per issue slot
__device__ __forceinline__ ull pk2(float x) {
    ull r; asm("mov.b64 %0,{%1,%1};" : "=l"(r) : "f"(x)); return r;
}
__device__ __forceinline__ void fma2(ull& d, ull a, ull b) {
    asm("fma.rn.f32x2 %0,%1,%2,%0;" : "+l"(d) : "l"(a), "l"(b));
}
__device__ __forceinline__ float2 up2(ull v) {
    float2 r; asm("mov.b64 {%0,%1},%2;" : "=f"(r.x), "=f"(r.y) : "l"(v)); return r;
}

// ---------------- weight folding (3 edge-conv layers + GAT weights) ----------------
struct FoldW { const float* w[18]; const float* wg; const float* as; const float* ad; };

__global__ void fold_kernel(FoldW fw, float* __restrict__ Wn, float* __restrict__ We,
                            float* __restrict__ bp, float* __restrict__ Wstk,
                            float* __restrict__ avec) {
    int L = blockIdx.y;
    int t = blockIdx.x * 256 + threadIdx.x;
    if (L < 3) {
        if (t >= 4480) return;
        const float* wn = fw.w[6 * L + 0];
        const float* bn = fw.w[6 * L + 1];
        const float* we = fw.w[6 * L + 2];
        const float* be = fw.w[6 * L + 3];
        const float* wc = fw.w[6 * L + 4];
        const float* bc = fw.w[6 * L + 5];
        if (t < 4096) {
            int r = t >> 6, c = t & 63;
            float s = 0.f;
            #pragma unroll 8
            for (int k = 0; k < 64; k++) s += wn[r * 64 + k] * wc[k * 64 + c];
            Wn[L * 4096 + t] = s;
        } else if (t < 4416) {
            int u = t - 4096;
            int j = u >> 6, c = u & 63;
            float s = 0.f;
            #pragma unroll 8
            for (int k = 0; k < 64; k++) s += we[j * 64 + k] * wc[(64 + k) * 64 + c];
            We[L * 320 + u] = s;
        } else {
            int c = t - 4416;
            float s = bc[c];
            #pragma unroll 8
            for (int k = 0; k < 64; k++)
                s += bn[k] * wc[k * 64 + c] + be[k] * wc[(64 + k) * 64 + c];
            bp[L * 64 + c] = s;
        }
    } else {
        if (t < 8192) {
            int k = t >> 6, c = t & 63;
            Wstk[t] = (k < 64) ? fw.wg[k * 128 + c] : fw.wg[(k - 64) * 128 + 64 + c];
        } else if (t < 8448) {
            int u = t - 8192;          // 0..255
            int vec = u >> 6;          // 0:avS0 1:avS1 2:avD0 3:avD1
            int k = u & 63;
            int hd = vec & 1;
            const float* att = (vec < 2) ? fw.as : fw.ad;
            float s = 0.f;
            #pragma unroll 8
            for (int c = 0; c < 64; c++) s += fw.wg[k * 128 + hd * 64 + c] * att[hd * 64 + c];
            avec[u] = s;
        }
    }
}

// ---------------- zero fill ----------------
__global__ void zero4_kernel(float4* __restrict__ p, int n4) {
    float4 z = make_float4(0.f, 0.f, 0.f, 0.f);
    for (int i = blockIdx.x * blockDim.x + threadIdx.x; i < n4; i += gridDim.x * blockDim.x)
        p[i] = z;
}

// ---------------- CSR build ----------------
__global__ void count_kernel(const int* __restrict__ dst, int* __restrict__ cnt) {
    int i = blockIdx.x * blockDim.x + threadIdx.x;
    if (i * 4 >= EE) return;
    int4 d = ((const int4*)dst)[i];
    atomicAdd(&cnt[d.x], 1);
    atomicAdd(&cnt[d.y], 1);
    atomicAdd(&cnt[d.z], 1);
    atomicAdd(&cnt[d.w], 1);
}

__global__ void scan_part(const int* __restrict__ cnt, int* __restrict__ bsum) {
    __shared__ int wsum[8];
    int b = blockIdx.x, t = threadIdx.x;
    int lane = t & 31, wid = t >> 5;
    int idx = b * SCAN_CHUNK + t * 4;
    int s = 0;
    if (idx < NN) {
        int4 v = *(const int4*)(cnt + idx);
        s = v.x + v.y + v.z + v.w;
    }
    #pragma unroll
    for (int o = 16; o; o >>= 1) s += __shfl_xor_sync(0xffffffffu, s, o);
    if (lane == 0) wsum[wid] = s;
    __syncthreads();
    if (t == 0) {
        int tot = 0;
        #pragma unroll
        for (int w = 0; w < 8; w++) tot += wsum[w];
        bsum[b] = tot;
    }
}

__global__ void scan_top(const int* __restrict__ bsum, int* __restrict__ boff) {
    __shared__ int wtot[4];
    int t = threadIdx.x;           // 128 threads
    int lane = t & 31, wid = t >> 5;
    int v = (t < SCAN_NB) ? bsum[t] : 0;
    int incl = v;
    #pragma unroll
    for (int o = 1; o < 32; o <<= 1) {
        int u = __shfl_up_sync(0xffffffffu, incl, o);
        if (lane >= o) incl += u;
    }
    if (lane == 31) wtot[wid] = incl;
    __syncthreads();
    int woff = 0;
    for (int w = 0; w < wid; w++) woff += wtot[w];
    if (t < SCAN_NB) boff[t] = woff + incl - v;
}

__global__ void scan_final(const int* __restrict__ cnt, const int* __restrict__ boff,
                           int* __restrict__ rowptr) {
    __shared__ int wsum[8];
    int b = blockIdx.x, t = threadIdx.x;
    int lane = t & 31, wid = t >> 5;
    int idx = b * SCAN_CHUNK + t * 4;
    int v[4] = {0, 0, 0, 0};
    if (idx < NN) {
        int4 d = *(const int4*)(cnt + idx);
        v[0] = d.x; v[1] = d.y; v[2] = d.z; v[3] = d.w;
    }
    #pragma unroll
    for (int j = 1; j < 4; j++) v[j] += v[j - 1];
    int tot = v[3];
    int incl = tot;
    #pragma unroll
    for (int o = 1; o < 32; o <<= 1) {
        int u = __shfl_up_sync(0xffffffffu, incl, o);
        if (lane >= o) incl += u;
    }
    if (lane == 31) wsum[wid] = incl;
    __syncthreads();
    int woff = 0;
    for (int w = 0; w < wid; w++) woff += wsum[w];
    int excl = boff[b] + woff + incl - tot;
    if (idx < NN) {
        #pragma unroll
        for (int j = 0; j < 4; j++) rowptr[idx + j + 1] = excl + v[j];
    }
    if (b == 0 && t == 0) rowptr[0] = 0;
}

__device__ __forceinline__ void scat1(int d, int s, int e, const int* __restrict__ rowptr,
                                      int* __restrict__ cnt, int* __restrict__ csr_src,
                                      const float* __restrict__ ea, float* __restrict__ S) {
    int pos = atomicAdd(&cnt[d], -1) - 1;
    csr_src[rowptr[d] + pos] = s;
    const float* eap = ea + (size_t)e * 5;
    #pragma unroll
    for (int k = 0; k < 5; k++) atomicAdd(&S[d * 5 + k], eap[k]);
}

__global__ void scatter_kernel(const int* __restrict__ src, const int* __restrict__ dst,
                               const int* __restrict__ rowptr, int* __restrict__ cnt,
                               int* __restrict__ csr_src, const float* __restrict__ ea,
                               float* __restrict__ S) {
    int i = blockIdx.x * blockDim.x + threadIdx.x;
    if (i * 4 >= EE) return;
    int4 d4 = ((const int4*)dst)[i];
    int4 s4 = ((const int4*)src)[i];
    int e = i * 4;
    scat1(d4.x, s4.x, e + 0, rowptr, cnt, csr_src, ea, S);
    scat1(d4.y, s4.y, e + 1, rowptr, cnt, csr_src, ea, S);
    scat1(d4.z, s4.z, e + 2, rowptr, cnt, csr_src, ea, S);
    scat1(d4.w, s4.w, e + 3, rowptr, cnt, csr_src, ea, S);
}

// ---------------- dense GEMM: 256x64 tile, 8x8/thread, f32x2, A streamed ----------------
__global__ __launch_bounds__(256) void gemm_big(
    const float* __restrict__ A, const float* __restrict__ W, float* __restrict__ C,
    int n, int relu) {
    __shared__ float Ws[64][64];   // 16KB
    int n0 = blockIdx.x << 8;
    int t = threadIdx.x;
    int tx = t & 7, ty = t >> 3;

    #pragma unroll
    for (int i = 0; i < 4; i++) {
        int idx = t + i * 256;
        int k = idx >> 4;
        int c4 = (idx & 15) << 2;
        *(float4*)&Ws[k][c4] = *(const float4*)(W + (size_t)k * 64 + c4);
    }
    __syncthreads();

    int r0 = n0 + ty * 8;
    ull acc[8][4];
    #pragma unroll
    for (int i = 0; i < 8; i++)
        #pragma unroll
        for (int j = 0; j < 4; j++) acc[i][j] = 0ull;

    for (int kc = 0; kc < 64; kc += 4) {
        float4 a[8];
        #pragma unroll
        for (int i = 0; i < 8; i++) {
            int row = r0 + i;
            float4 v = make_float4(0.f, 0.f, 0.f, 0.f);
            if (row < n) v = *(const float4*)(A + (size_t)row * 64 + kc);
            if (relu) {
                v.x = fmaxf(v.x, 0.f); v.y = fmaxf(v.y, 0.f);
                v.z = fmaxf(v.z, 0.f); v.w = fmaxf(v.w, 0.f);
            }
            a[i] = v;
        }
        #pragma unroll
        for (int kk = 0; kk < 4; kk++) {
            const ull* bb = (const ull*)&Ws[kc + kk][tx * 8];
            ull b0 = bb[0], b1 = bb[1], b2 = bb[2], b3 = bb[3];
            #pragma unroll
            for (int i = 0; i < 8; i++) {
                float av = (kk == 0) ? a[i].x : (kk == 1) ? a[i].y : (kk == 2) ? a[i].z : a[i].w;
                ull a2 = pk2(av);
                fma2(acc[i][0], a2, b0);
                fma2(acc[i][1], a2, b1);
                fma2(acc[i][2], a2, b2);
                fma2(acc[i][3], a2, b3);
            }
        }
    }

    #pragma unroll
    for (int i = 0; i < 8; i++) {
        int row = r0 + i;
        if (row < n) {
            float2 p0 = up2(acc[i][0]), p1 = up2(acc[i][1]);
            float2 p2 = up2(acc[i][2]), p3 = up2(acc[i][3]);
            *(float4*)(C + (size_t)row * 64 + tx * 8) =
                make_float4(p0.x, p0.y, p1.x, p1.y);
            *(float4*)(C + (size_t)row * 64 + tx * 8 + 4) =
                make_float4(p2.x, p2.y, p3.x, p3.y);
        }
    }
}

// ---------------- edge aggregation (CSR, warp per node) ----------------
__global__ void agg_kernel(const float* __restrict__ p, const int* __restrict__ csr_src,
                           const int* __restrict__ rowptr, const float* __restrict__ S,
                           const float* __restrict__ We, const float* __restrict__ bp,
                           float* __restrict__ out) {
    __shared__ float sWe[320];
    __shared__ float sbp[64];
    int t = threadIdx.x;
    for (int i = t; i < 384; i += 256) {
        if (i < 320) sWe[i] = We[i];
        else sbp[i - 320] = bp[i - 320];
    }
    __syncthreads();

    int n = blockIdx.x * 8 + (t >> 5);
    int lane = t & 31;
    int start = rowptr[n], end = rowptr[n + 1];
    float s0 = S[n * 5 + 0], s1 = S[n * 5 + 1], s2 = S[n * 5 + 2],
          s3 = S[n * 5 + 3], s4 = S[n * 5 + 4];
    float deg = (float)(end - start);
    int c = lane, c2 = lane + 32;
    float acc0 = deg * sbp[c] + s0 * sWe[c] + s1 * sWe[64 + c] + s2 * sWe[128 + c] +
                 s3 * sWe[192 + c] + s4 * sWe[256 + c];
    float acc1 = deg * sbp[c2] + s0 * sWe[c2] + s1 * sWe[64 + c2] + s2 * sWe[128 + c2] +
                 s3 * sWe[192 + c2] + s4 * sWe[256 + c2];

    int j = start;
    for (; j + 1 < end; j += 2) {
        int sa = csr_src[j], sb = csr_src[j + 1];
        const float* pa = p + (size_t)sa * 64;
        const float* pb = p + (size_t)sb * 64;
        acc0 += pa[c] + pb[c];
        acc1 += pa[c2] + pb[c2];
    }
    if (j < end) {
        int sa = csr_src[j];
        acc0 += p[(size_t)sa * 64 + c];
        acc1 += p[(size_t)sa * 64 + c2];
    }
    out[(size_t)n * 64 + c] = acc0;
    out[(size_t)n * 64 + c2] = acc1;
}

// ---------------- attention coefficients from h3 (pre-relu stored): a = relu(h3)·avec ----------------
__global__ void attn_kernel(const float* __restrict__ h, const float* __restrict__ avec,
                            float* __restrict__ aS, float* __restrict__ aD) {
    int n = blockIdx.x * 8 + (threadIdx.x >> 5);
    int lane = threadIdx.x & 31;
    const float* hr = h + (size_t)n * 64;
    float r0 = fmaxf(hr[lane], 0.f);
    float r1 = fmaxf(hr[lane + 32], 0.f);
    float vS0 = r0 * avec[lane] + r1 * avec[lane + 32];
    float vS1 = r0 * avec[64 + lane] + r1 * avec[96 + lane];
    float vD0 = r0 * avec[128 + lane] + r1 * avec[160 + lane];
    float vD1 = r0 * avec[192 + lane] + r1 * avec[224 + lane];
    #pragma unroll
    for (int o = 16; o; o >>= 1) {
        vS0 += __shfl_xor_sync(0xffffffffu, vS0, o);
        vS1 += __shfl_xor_sync(0xffffffffu, vS1, o);
        vD0 += __shfl_xor_sync(0xffffffffu, vD0, o);
        vD1 += __shfl_xor_sync(0xffffffffu, vD1, o);
    }
    if (lane == 0) {
        aS[n * 2] = vS0; aS[n * 2 + 1] = vS1;
        aD[n * 2] = vD0; aD[n * 2 + 1] = vD1;
    }
}

// ---------------- GAT aggregation: softmax-weighted sum of relu(h3) rows -> z[N,128] ----------------
__global__ void gat_agg_kernel(const int* __restrict__ csr_src, const int* __restrict__ rowptr,
                               const float2* __restrict__ aS, const float2* __restrict__ aD,
                               const float* __restrict__ h, float* __restrict__ z) {
    int n = blockIdx.x * 8 + (threadIdx.x >> 5);
    int lane = threadIdx.x & 31;
    int start = rowptr[n], end = rowptr[n + 1];
    float2 ad = aD[n];
    float m0 = -1e30f, m1 = -1e30f;
    for (int j = start; j < end; j++) {
        float2 as = aS[csr_src[j]];
        m0 = fmaxf(m0, lrelu(as.x + ad.x));
        m1 = fmaxf(m1, lrelu(as.y + ad.y));
    }
    float acc0 = 0.f, acc1 = 0.f, acc2 = 0.f, acc3 = 0.f, den0 = 0.f, den1 = 0.f;
    for (int j = start; j < end; j++) {
        int s = csr_src[j];
        float2 as = aS[s];
        float w0 = __expf(lrelu(as.x + ad.x) - m0);
        float w1 = __expf(lrelu(as.y + ad.y) - m1);
        den0 += w0;
        den1 += w1;
        const float* hs = h + (size_t)s * 64;
        float v0 = fmaxf(hs[lane], 0.f);
        float v1 = fmaxf(hs[lane + 32], 0.f);
        acc0 += w0 * v0;
        acc1 += w0 * v1;
        acc2 += w1 * v0;
        acc3 += w1 * v1;
    }
    float id0 = 0.5f / (den0 + 1e-16f);
    float id1 = 0.5f / (den1 + 1e-16f);
    float* zn = z + (size_t)n * 128;
    zn[lane]      = acc0 * id0;
    zn[lane + 32] = acc1 * id0;
    zn[lane + 64] = acc2 * id1;
    zn[lane + 96] = acc3 * id1;
}

// ---------------- final GEMM: out = z[N,128] @ Wstk[128,64] + b_gat ----------------
__global__ __launch_bounds__(256) void gemm_fin(
    const float* __restrict__ z, const float* __restrict__ Wstk,
    const float* __restrict__ bias, float* __restrict__ out, int n) {
    __shared__ float Ws[128][64];   // 32KB
    int n0 = blockIdx.x << 8;
    int t = threadIdx.x;
    int tx = t & 7, ty = t >> 3;

    #pragma unroll
    for (int i = 0; i < 8; i++) {
        int idx = t + i * 256;
        int k = idx >> 4;
        int c4 = (idx & 15) << 2;
        *(float4*)&Ws[k][c4] = *(const float4*)(Wstk + k * 64 + c4);
    }
    __syncthreads();

    int r0 = n0 + ty * 8;
    ull acc[8][4];
    #pragma unroll
    for (int i = 0; i < 8; i++)
        #pragma unroll
        for (int j = 0; j < 4; j++) acc[i][j] = 0ull;

    for (int kc = 0; kc < 128; kc += 4) {
        float4 a[8];
        #pragma unroll
        for (int i = 0; i < 8; i++) {
            int row = r0 + i;
            a[i] = (row < n) ? *(const float4*)(z + (size_t)row * 128 + kc)
                             : make_float4(0.f, 0.f, 0.f, 0.f);
        }
        #pragma unroll
        for (int kk = 0; kk < 4; kk++) {
            const ull* bb = (const ull*)&Ws[kc + kk][tx * 8];
            ull b0 = bb[0], b1 = bb[1], b2 = bb[2], b3 = bb[3];
            #pragma unroll
            for (int i = 0; i < 8; i++) {
                float av = (kk == 0) ? a[i].x : (kk == 1) ? a[i].y : (kk == 2) ? a[i].z : a[i].w;
                ull a2 = pk2(av);
                fma2(acc[i][0], a2, b0);
                fma2(acc[i][1], a2, b1);
                fma2(acc[i][2], a2, b2);
                fma2(acc[i][3], a2, b3);
            }
        }
    }

    float4 bA = *(const float4*)(bias + tx * 8);
    float4 bB = *(const float4*)(bias + tx * 8 + 4);
    #pragma unroll
    for (int i = 0; i < 8; i++) {
        int row = r0 + i;
        if (row < n) {
            float2 p0 = up2(acc[i][0]), p1 = up2(acc[i][1]);
            float2 p2 = up2(acc[i][2]), p3 = up2(acc[i][3]);
            *(float4*)(out + (size_t)row * 64 + tx * 8) =
                make_float4(p0.x + bA.x, p0.y + bA.y, p1.x + bA.z, p1.y + bA.w);
            *(float4*)(out + (size_t)row * 64 + tx * 8 + 4) =
                make_float4(p2.x + bB.x, p2.y + bB.y, p3.x + bB.z, p3.y + bB.w);
        }
    }
}

// ---------------- launch ----------------
extern "C" void kernel_launch(void* const* d_in, const int* in_sizes, int n_in,
                              void* d_out, int out_size) {
    const float* x = (const float*)d_in[0];
    const int* ei = (const int*)d_in[1];
    const float* ea = (const float*)d_in[2];
    const int* src = ei;
    const int* dst = ei + EE;
    FoldW fw;
    for (int i = 0; i < 18; i++) fw.w[i] = (const float*)d_in[3 + i];
    fw.wg = (const float*)d_in[21];
    fw.as = (const float*)d_in[22];
    fw.ad = (const float*)d_in[23];
    const float* b_gat = (const float*)d_in[24];
    float* out = (float*)d_out;

    float *h1, *h2, *p, *z, *asrc, *adst, *Wn, *We, *bp, *Wstk, *avec, *S;
    int *cnt, *rowptr, *csr_src, *bsum, *boff;
    cudaGetSymbolAddress((void**)&h1, g_h1);
    cudaGetSymbolAddress((void**)&h2, g_h2);
    cudaGetSymbolAddress((void**)&p, g_p);
    cudaGetSymbolAddress((void**)&z, g_z);
    cudaGetSymbolAddress((void**)&asrc, g_asrc);
    cudaGetSymbolAddress((void**)&adst, g_adst);
    cudaGetSymbolAddress((void**)&Wn, g_Wn);
    cudaGetSymbolAddress((void**)&We, g_We);
    cudaGetSymbolAddress((void**)&bp, g_bp);
    cudaGetSymbolAddress((void**)&Wstk, g_Wstk);
    cudaGetSymbolAddress((void**)&avec, g_avec);
    cudaGetSymbolAddress((void**)&cnt, g_cnt);
    cudaGetSymbolAddress((void**)&rowptr, g_rowptr);
    cudaGetSymbolAddress((void**)&csr_src, g_csr_src);
    cudaGetSymbolAddress((void**)&S, g_S);
    cudaGetSymbolAddress((void**)&bsum, g_bsum);
    cudaGetSymbolAddress((void**)&boff, g_boff);

    const int NB = NN / 8;                 // 12500 warp-per-node blocks
    const int gbx = (NN + 255) / 256;      // 391 gemm row tiles

    // Launch order keeps the first gemm_big in profile slot 6 (ncu -s 5 -c 1).
    zero4_kernel<<<98, 256>>>((float4*)cnt, NN / 4);                           // 1
    count_kernel<<<(EE / 4 + 255) / 256, 256>>>(dst, cnt);                     // 2
    scan_part<<<SCAN_NB, 256>>>(cnt, bsum);                                    // 3
    scan_top<<<1, 128>>>(bsum, boff);                                          // 4
    fold_kernel<<<dim3(33, 4), 256>>>(fw, Wn, We, bp, Wstk, avec);             // 5
    gemm_big<<<gbx, 256>>>(x, Wn + 0 * 4096, p, NN, 0);                        // 6 (profiled)
    scan_final<<<SCAN_NB, 256>>>(cnt, boff, rowptr);                           // 7
    zero4_kernel<<<489, 256>>>((float4*)S, NN * 5 / 4);                        // 8
    scatter_kernel<<<(EE / 4 + 255) / 256, 256>>>(src, dst, rowptr, cnt,       // 9
                                                  csr_src, ea, S);

    agg_kernel<<<NB, 256>>>(p, csr_src, rowptr, S, We + 0 * 320, bp + 0 * 64, h1);
    gemm_big<<<gbx, 256>>>(h1, Wn + 1 * 4096, p, NN, 1);
    agg_kernel<<<NB, 256>>>(p, csr_src, rowptr, S, We + 1 * 320, bp + 1 * 64, h2);
    gemm_big<<<gbx, 256>>>(h2, Wn + 2 * 4096, p, NN, 1);
    agg_kernel<<<NB, 256>>>(p, csr_src, rowptr, S, We + 2 * 320, bp + 2 * 64, h1);

    // ---- GAT tail: attention coeffs on h3, aggregate relu(h3), project once ----
    attn_kernel<<<NB, 256>>>(h1, avec, asrc, adst);
    gat_agg_kernel<<<NB, 256>>>(csr_src, rowptr, (const float2*)asrc, (const float2*)adst,
                                h1, z);
    gemm_fin<<<(NN + 255) / 256, 256>>>(z, Wstk, b_gat, out, NN);
}

// round 10
// speedup vs baseline: 1.4209x; 1.0284x over previous
#include <cuda_runtime.h>

#define NN 100000
#define EE 800000
#define SCAN_CHUNK 1024
#define SCAN_NB 98   // 98*1024 = 100352 >= NN

typedef unsigned long long ull;

// ---------------- scratch (device globals) ----------------
__device__ float g_h1[NN * 64];
__device__ float g_h2[NN * 64];
__device__ float g_h3[NN * 64];
__device__ float g_z[NN * 128];
__device__ float g_asrc[NN * 2];
__device__ float g_adst[NN * 2];
__device__ float g_Wn[3][4096];
__device__ float g_We[3][320];
__device__ float g_bp[3][64];
__device__ float g_Wstk[8192];     // [k][c]: k<64 -> Wg[k][c] ; k>=64 -> Wg[k-64][64+c]
__device__ float g_avec[256];      // avS0[64] avS1[64] avD0[64] avD1[64]  (Wg @ att vectors)
__device__ int g_cnt[NN];
__device__ int g_rowptr[NN + 4];
__device__ int g_csr_src[EE];
__device__ float g_S[NN * 5];
__device__ int g_bsum[SCAN_NB];
__device__ int g_boff[SCAN_NB];

__device__ __forceinline__ float lrelu(float x) { return x > 0.f ? x : 0.2f * x; }

// f32x2 packed math (Blackwell): 2 fp32 FMAs per issue slot
__device__ __forceinline__ ull pk2(float x) {
    ull r; asm("mov.b64 %0,{%1,%1};" : "=l"(r) : "f"(x)); return r;
}
__device__ __forceinline__ void fma2(ull& d, ull a, ull b) {
    asm("fma.rn.f32x2 %0,%1,%2,%0;" : "+l"(d) : "l"(a), "l"(b));
}
__device__ __forceinline__ float2 up2(ull v) {
    float2 r; asm("mov.b64 {%0,%1},%2;" : "=f"(r.x), "=f"(r.y) : "l"(v)); return r;
}

// ---------------- weight folding (3 edge-conv layers + GAT weights) ----------------
struct FoldW { const float* w[18]; const float* wg; const float* as; const float* ad; };

__global__ void fold_kernel(FoldW fw, float* __restrict__ Wn, float* __restrict__ We,
                            float* __restrict__ bp, float* __restrict__ Wstk,
                            float* __restrict__ avec) {
    int L = blockIdx.y;
    int t = blockIdx.x * 256 + threadIdx.x;
    if (L < 3) {
        if (t >= 4480) return;
        const float* wn = fw.w[6 * L + 0];
        const float* bn = fw.w[6 * L + 1];
        const float* we = fw.w[6 * L + 2];
        const float* be = fw.w[6 * L + 3];
        const float* wc = fw.w[6 * L + 4];
        const float* bc = fw.w[6 * L + 5];
        if (t < 4096) {
            int r = t >> 6, c = t & 63;
            float s = 0.f;
            #pragma unroll 8
            for (int k = 0; k < 64; k++) s += wn[r * 64 + k] * wc[k * 64 + c];
            Wn[L * 4096 + t] = s;
        } else if (t < 4416) {
            int u = t - 4096;
            int j = u >> 6, c = u & 63;
            float s = 0.f;
            #pragma unroll 8
            for (int k = 0; k < 64; k++) s += we[j * 64 + k] * wc[(64 + k) * 64 + c];
            We[L * 320 + u] = s;
        } else {
            int c = t - 4416;
            float s = bc[c];
            #pragma unroll 8
            for (int k = 0; k < 64; k++)
                s += bn[k] * wc[k * 64 + c] + be[k] * wc[(64 + k) * 64 + c];
            bp[L * 64 + c] = s;
        }
    } else {
        if (t < 8192) {
            int k = t >> 6, c = t & 63;
            Wstk[t] = (k < 64) ? fw.wg[k * 128 + c] : fw.wg[(k - 64) * 128 + 64 + c];
        } else if (t < 8448) {
            int u = t - 8192;          // 0..255
            int vec = u >> 6;          // 0:avS0 1:avS1 2:avD0 3:avD1
            int k = u & 63;
            int hd = vec & 1;
            const float* att = (vec < 2) ? fw.as : fw.ad;
            float s = 0.f;
            #pragma unroll 8
            for (int c = 0; c < 64; c++) s += fw.wg[k * 128 + hd * 64 + c] * att[hd * 64 + c];
            avec[u] = s;
        }
    }
}

// ---------------- zero fill ----------------
__global__ void zero4_kernel(float4* __restrict__ p, int n4) {
    float4 z = make_float4(0.f, 0.f, 0.f, 0.f);
    for (int i = blockIdx.x * blockDim.x + threadIdx.x; i < n4; i += gridDim.x * blockDim.x)
        p[i] = z;
}

// ---------------- CSR build ----------------
__global__ void count_kernel(const int* __restrict__ dst, int* __restrict__ cnt) {
    int i = blockIdx.x * blockDim.x + threadIdx.x;
    if (i * 4 >= EE) return;
    int4 d = ((const int4*)dst)[i];
    atomicAdd(&cnt[d.x], 1);
    atomicAdd(&cnt[d.y], 1);
    atomicAdd(&cnt[d.z], 1);
    atomicAdd(&cnt[d.w], 1);
}

__global__ void scan_part(const int* __restrict__ cnt, int* __restrict__ bsum) {
    __shared__ int wsum[8];
    int b = blockIdx.x, t = threadIdx.x;
    int lane = t & 31, wid = t >> 5;
    int idx = b * SCAN_CHUNK + t * 4;
    int s = 0;
    if (idx < NN) {
        int4 v = *(const int4*)(cnt + idx);
        s = v.x + v.y + v.z + v.w;
    }
    #pragma unroll
    for (int o = 16; o; o >>= 1) s += __shfl_xor_sync(0xffffffffu, s, o);
    if (lane == 0) wsum[wid] = s;
    __syncthreads();
    if (t == 0) {
        int tot = 0;
        #pragma unroll
        for (int w = 0; w < 8; w++) tot += wsum[w];
        bsum[b] = tot;
    }
}

__global__ void scan_top(const int* __restrict__ bsum, int* __restrict__ boff) {
    __shared__ int wtot[4];
    int t = threadIdx.x;           // 128 threads
    int lane = t & 31, wid = t >> 5;
    int v = (t < SCAN_NB) ? bsum[t] : 0;
    int incl = v;
    #pragma unroll
    for (int o = 1; o < 32; o <<= 1) {
        int u = __shfl_up_sync(0xffffffffu, incl, o);
        if (lane >= o) incl += u;
    }
    if (lane == 31) wtot[wid] = incl;
    __syncthreads();
    int woff = 0;
    for (int w = 0; w < wid; w++) woff += wtot[w];
    if (t < SCAN_NB) boff[t] = woff + incl - v;
}

__global__ void scan_final(const int* __restrict__ cnt, const int* __restrict__ boff,
                           int* __restrict__ rowptr) {
    __shared__ int wsum[8];
    int b = blockIdx.x, t = threadIdx.x;
    int lane = t & 31, wid = t >> 5;
    int idx = b * SCAN_CHUNK + t * 4;
    int v[4] = {0, 0, 0, 0};
    if (idx < NN) {
        int4 d = *(const int4*)(cnt + idx);
        v[0] = d.x; v[1] = d.y; v[2] = d.z; v[3] = d.w;
    }
    #pragma unroll
    for (int j = 1; j < 4; j++) v[j] += v[j - 1];
    int tot = v[3];
    int incl = tot;
    #pragma unroll
    for (int o = 1; o < 32; o <<= 1) {
        int u = __shfl_up_sync(0xffffffffu, incl, o);
        if (lane >= o) incl += u;
    }
    if (lane == 31) wsum[wid] = incl;
    __syncthreads();
    int woff = 0;
    for (int w = 0; w < wid; w++) woff += wsum[w];
    int excl = boff[b] + woff + incl - tot;
    if (idx < NN) {
        #pragma unroll
        for (int j = 0; j < 4; j++) rowptr[idx + j + 1] = excl + v[j];
    }
    if (b == 0 && t == 0) rowptr[0] = 0;
}

__device__ __forceinline__ void scat1(int d, int s, int e, const int* __restrict__ rowptr,
                                      int* __restrict__ cnt, int* __restrict__ csr_src,
                                      const float* __restrict__ ea, float* __restrict__ S) {
    int pos = atomicAdd(&cnt[d], -1) - 1;
    csr_src[rowptr[d] + pos] = s;
    const float* eap = ea + (size_t)e * 5;
    #pragma unroll
    for (int k = 0; k < 5; k++) atomicAdd(&S[d * 5 + k], eap[k]);
}

__global__ void scatter_kernel(const int* __restrict__ src, const int* __restrict__ dst,
                               const int* __restrict__ rowptr, int* __restrict__ cnt,
                               int* __restrict__ csr_src, const float* __restrict__ ea,
                               float* __restrict__ S) {
    int i = blockIdx.x * blockDim.x + threadIdx.x;
    if (i * 4 >= EE) return;
    int4 d4 = ((const int4*)dst)[i];
    int4 s4 = ((const int4*)src)[i];
    int e = i * 4;
    scat1(d4.x, s4.x, e + 0, rowptr, cnt, csr_src, ea, S);
    scat1(d4.y, s4.y, e + 1, rowptr, cnt, csr_src, ea, S);
    scat1(d4.z, s4.z, e + 2, rowptr, cnt, csr_src, ea, S);
    scat1(d4.w, s4.w, e + 3, rowptr, cnt, csr_src, ea, S);
}

// ---------------- fused layer: gather 64 nodes -> smem qT -> block mini-GEMM ----------------
// out[n] = (Σ_src relu?(hin[src])) @ Wn + S[n] @ We + deg(n)*bp      [stored pre-relu]
// qT rows 0..63 = q transposed; 64..68 = S[n][0..4]; 69 = deg.
// Ws rows 0..63 = Wn; 64..68 = We; 69 = bp.  Single 70-deep k loop does all terms.
__global__ __launch_bounds__(256) void fused_layer(
    const float* __restrict__ hin, const int* __restrict__ csr_src,
    const int* __restrict__ rowptr, const float* __restrict__ S,
    const float* __restrict__ Wn, const float* __restrict__ We,
    const float* __restrict__ bp, float* __restrict__ out, int relu) {
    __shared__ float qT[70][68];   // row stride 272B (16-aligned)
    __shared__ float Ws[70][64];
    int t = threadIdx.x;
    int n0 = blockIdx.x << 6;

    // load weights (70x64 = 1120 float4 quads... 70*16=1120 float4)
    #pragma unroll
    for (int i = 0; i < 5; i++) {
        int idx = t + i * 256;
        if (idx < 1120) {
            int r = idx >> 4, c4 = (idx & 15) << 2;
            float4 v;
            if (r < 64) v = *(const float4*)(Wn + r * 64 + c4);
            else if (r < 69) v = *(const float4*)(We + (r - 64) * 64 + c4);
            else v = *(const float4*)(bp + c4);
            *(float4*)&Ws[r][c4] = v;
        }
    }

    // phase 1: each warp gathers 8 nodes
    int w = t >> 5, lane = t & 31;
    #pragma unroll
    for (int i = 0; i < 8; i++) {
        int nl = w * 8 + i;
        int n = n0 + nl;
        float q0 = 0.f, q1 = 0.f, deg = 0.f, sv = 0.f;
        if (n < NN) {
            int start = rowptr[n], end = rowptr[n + 1];
            deg = (float)(end - start);
            int j = start;
            for (; j + 1 < end; j += 2) {
                const float* pa = hin + (size_t)csr_src[j] * 64;
                const float* pb = hin + (size_t)csr_src[j + 1] * 64;
                float a0 = pa[lane], a1 = pa[lane + 32];
                float b0 = pb[lane], b1 = pb[lane + 32];
                if (relu) {
                    a0 = fmaxf(a0, 0.f); a1 = fmaxf(a1, 0.f);
                    b0 = fmaxf(b0, 0.f); b1 = fmaxf(b1, 0.f);
                }
                q0 += a0 + b0;
                q1 += a1 + b1;
            }
            if (j < end) {
                const float* pa = hin + (size_t)csr_src[j] * 64;
                float a0 = pa[lane], a1 = pa[lane + 32];
                if (relu) { a0 = fmaxf(a0, 0.f); a1 = fmaxf(a1, 0.f); }
                q0 += a0;
                q1 += a1;
            }
            if (lane < 5) sv = S[(size_t)n * 5 + lane];
        }
        qT[lane][nl] = q0;
        qT[lane + 32][nl] = q1;
        if (lane < 5) qT[64 + lane][nl] = sv;
        if (lane == 5) qT[69][nl] = deg;
    }
    __syncthreads();

    // phase 2: 64x64 output, 70-deep, thread tile 4 rows x 4 cols
    int tcol = t & 15, trow = t >> 4;
    int r0 = trow << 2, c0 = tcol << 2;
    ull acc[4][2];
    #pragma unroll
    for (int i = 0; i < 4; i++) { acc[i][0] = 0ull; acc[i][1] = 0ull; }

    #pragma unroll 10
    for (int k = 0; k < 70; k++) {
        float4 a = *(float4*)&qT[k][r0];
        const ull* bb = (const ull*)&Ws[k][c0];
        ull b0 = bb[0], b1 = bb[1];
        ull a0 = pk2(a.x), a1 = pk2(a.y), a2 = pk2(a.z), a3 = pk2(a.w);
        fma2(acc[0][0], a0, b0); fma2(acc[0][1], a0, b1);
        fma2(acc[1][0], a1, b0); fma2(acc[1][1], a1, b1);
        fma2(acc[2][0], a2, b0); fma2(acc[2][1], a2, b1);
        fma2(acc[3][0], a3, b0); fma2(acc[3][1], a3, b1);
    }

    #pragma unroll
    for (int i = 0; i < 4; i++) {
        int n = n0 + r0 + i;
        if (n < NN) {
            float2 p0 = up2(acc[i][0]), p1 = up2(acc[i][1]);
            *(float4*)(out + (size_t)n * 64 + c0) = make_float4(p0.x, p0.y, p1.x, p1.y);
        }
    }
}

// ---------------- attention coefficients from h3 (pre-relu stored): a = relu(h3)·avec ----------------
__global__ void attn_kernel(const float* __restrict__ h, const float* __restrict__ avec,
                            float* __restrict__ aS, float* __restrict__ aD) {
    int n = blockIdx.x * 8 + (threadIdx.x >> 5);
    int lane = threadIdx.x & 31;
    const float* hr = h + (size_t)n * 64;
    float r0 = fmaxf(hr[lane], 0.f);
    float r1 = fmaxf(hr[lane + 32], 0.f);
    float vS0 = r0 * avec[lane] + r1 * avec[lane + 32];
    float vS1 = r0 * avec[64 + lane] + r1 * avec[96 + lane];
    float vD0 = r0 * avec[128 + lane] + r1 * avec[160 + lane];
    float vD1 = r0 * avec[192 + lane] + r1 * avec[224 + lane];
    #pragma unroll
    for (int o = 16; o; o >>= 1) {
        vS0 += __shfl_xor_sync(0xffffffffu, vS0, o);
        vS1 += __shfl_xor_sync(0xffffffffu, vS1, o);
        vD0 += __shfl_xor_sync(0xffffffffu, vD0, o);
        vD1 += __shfl_xor_sync(0xffffffffu, vD1, o);
    }
    if (lane == 0) {
        aS[n * 2] = vS0; aS[n * 2 + 1] = vS1;
        aD[n * 2] = vD0; aD[n * 2 + 1] = vD1;
    }
}

// ---------------- GAT aggregation: softmax-weighted sum of relu(h3) rows -> z[N,128] ----------------
__global__ void gat_agg_kernel(const int* __restrict__ csr_src, const int* __restrict__ rowptr,
                               const float2* __restrict__ aS, const float2* __restrict__ aD,
                               const float* __restrict__ h, float* __restrict__ z) {
    int n = blockIdx.x * 8 + (threadIdx.x >> 5);
    int lane = threadIdx.x & 31;
    int start = rowptr[n], end = rowptr[n + 1];
    float2 ad = aD[n];
    float m0 = -1e30f, m1 = -1e30f;
    for (int j = start; j < end; j++) {
        float2 as = aS[csr_src[j]];
        m0 = fmaxf(m0, lrelu(as.x + ad.x));
        m1 = fmaxf(m1, lrelu(as.y + ad.y));
    }
    float acc0 = 0.f, acc1 = 0.f, acc2 = 0.f, acc3 = 0.f, den0 = 0.f, den1 = 0.f;
    for (int j = start; j < end; j++) {
        int s = csr_src[j];
        float2 as = aS[s];
        float w0 = __expf(lrelu(as.x + ad.x) - m0);
        float w1 = __expf(lrelu(as.y + ad.y) - m1);
        den0 += w0;
        den1 += w1;
        const float* hs = h + (size_t)s * 64;
        float v0 = fmaxf(hs[lane], 0.f);
        float v1 = fmaxf(hs[lane + 32], 0.f);
        acc0 += w0 * v0;
        acc1 += w0 * v1;
        acc2 += w1 * v0;
        acc3 += w1 * v1;
    }
    float id0 = 0.5f / (den0 + 1e-16f);
    float id1 = 0.5f / (den1 + 1e-16f);
    float* zn = z + (size_t)n * 128;
    zn[lane]      = acc0 * id0;
    zn[lane + 32] = acc1 * id0;
    zn[lane + 64] = acc2 * id1;
    zn[lane + 96] = acc3 * id1;
}

// ---------------- final GEMM: out = z[N,128] @ Wstk[128,64] + b_gat ----------------
__global__ __launch_bounds__(256) void gemm_fin(
    const float* __restrict__ z, const float* __restrict__ Wstk,
    const float* __restrict__ bias, float* __restrict__ out, int n) {
    __shared__ float Ws[128][64];   // 32KB
    int n0 = blockIdx.x << 8;
    int t = threadIdx.x;
    int tx = t & 7, ty = t >> 3;

    #pragma unroll
    for (int i = 0; i < 8; i++) {
        int idx = t + i * 256;
        int k = idx >> 4;
        int c4 = (idx & 15) << 2;
        *(float4*)&Ws[k][c4] = *(const float4*)(Wstk + k * 64 + c4);
    }
    __syncthreads();

    int r0 = n0 + ty * 8;
    ull acc[8][4];
    #pragma unroll
    for (int i = 0; i < 8; i++)
        #pragma unroll
        for (int j = 0; j < 4; j++) acc[i][j] = 0ull;

    for (int kc = 0; kc < 128; kc += 4) {
        float4 a[8];
        #pragma unroll
        for (int i = 0; i < 8; i++) {
            int row = r0 + i;
            a[i] = (row < n) ? *(const float4*)(z + (size_t)row * 128 + kc)
                             : make_float4(0.f, 0.f, 0.f, 0.f);
        }
        #pragma unroll
        for (int kk = 0; kk < 4; kk++) {
            const ull* bb = (const ull*)&Ws[kc + kk][tx * 8];
            ull b0 = bb[0], b1 = bb[1], b2 = bb[2], b3 = bb[3];
            #pragma unroll
            for (int i = 0; i < 8; i++) {
                float av = (kk == 0) ? a[i].x : (kk == 1) ? a[i].y : (kk == 2) ? a[i].z : a[i].w;
                ull a2 = pk2(av);
                fma2(acc[i][0], a2, b0);
                fma2(acc[i][1], a2, b1);
                fma2(acc[i][2], a2, b2);
                fma2(acc[i][3], a2, b3);
            }
        }
    }

    float4 bA = *(const float4*)(bias + tx * 8);
    float4 bB = *(const float4*)(bias + tx * 8 + 4);
    #pragma unroll
    for (int i = 0; i < 8; i++) {
        int row = r0 + i;
        if (row < n) {
            float2 p0 = up2(acc[i][0]), p1 = up2(acc[i][1]);
            float2 p2 = up2(acc[i][2]), p3 = up2(acc[i][3]);
            *(float4*)(out + (size_t)row * 64 + tx * 8) =
                make_float4(p0.x + bA.x, p0.y + bA.y, p1.x + bA.z, p1.y + bA.w);
            *(float4*)(out + (size_t)row * 64 + tx * 8 + 4) =
                make_float4(p2.x + bB.x, p2.y + bB.y, p3.x + bB.z, p3.y + bB.w);
        }
    }
}

// ---------------- launch ----------------
extern "C" void kernel_launch(void* const* d_in, const int* in_sizes, int n_in,
                              void* d_out, int out_size) {
    const float* x = (const float*)d_in[0];
    const int* ei = (const int*)d_in[1];
    const float* ea = (const float*)d_in[2];
    const int* src = ei;
    const int* dst = ei + EE;
    FoldW fw;
    for (int i = 0; i < 18; i++) fw.w[i] = (const float*)d_in[3 + i];
    fw.wg = (const float*)d_in[21];
    fw.as = (const float*)d_in[22];
    fw.ad = (const float*)d_in[23];
    const float* b_gat = (const float*)d_in[24];
    float* out = (float*)d_out;

    float *h1, *h2, *h3, *z, *asrc, *adst, *Wn, *We, *bp, *Wstk, *avec, *S;
    int *cnt, *rowptr, *csr_src, *bsum, *boff;
    cudaGetSymbolAddress((void**)&h1, g_h1);
    cudaGetSymbolAddress((void**)&h2, g_h2);
    cudaGetSymbolAddress((void**)&h3, g_h3);
    cudaGetSymbolAddress((void**)&z, g_z);
    cudaGetSymbolAddress((void**)&asrc, g_asrc);
    cudaGetSymbolAddress((void**)&adst, g_adst);
    cudaGetSymbolAddress((void**)&Wn, g_Wn);
    cudaGetSymbolAddress((void**)&We, g_We);
    cudaGetSymbolAddress((void**)&bp, g_bp);
    cudaGetSymbolAddress((void**)&Wstk, g_Wstk);
    cudaGetSymbolAddress((void**)&avec, g_avec);
    cudaGetSymbolAddress((void**)&cnt, g_cnt);
    cudaGetSymbolAddress((void**)&rowptr, g_rowptr);
    cudaGetSymbolAddress((void**)&csr_src, g_csr_src);
    cudaGetSymbolAddress((void**)&S, g_S);
    cudaGetSymbolAddress((void**)&bsum, g_bsum);
    cudaGetSymbolAddress((void**)&boff, g_boff);

    const int NB = NN / 8;                 // 12500 warp-per-node blocks
    const int FB = (NN + 63) / 64;         // 1563 fused-layer blocks

    // ---- CSR build + weight folding ----
    zero4_kernel<<<98, 256>>>((float4*)cnt, NN / 4);
    count_kernel<<<(EE / 4 + 255) / 256, 256>>>(dst, cnt);
    scan_part<<<SCAN_NB, 256>>>(cnt, bsum);
    scan_top<<<1, 128>>>(bsum, boff);
    fold_kernel<<<dim3(33, 4), 256>>>(fw, Wn, We, bp, Wstk, avec);
    scan_final<<<SCAN_NB, 256>>>(cnt, boff, rowptr);
    zero4_kernel<<<489, 256>>>((float4*)S, NN * 5 / 4);
    scatter_kernel<<<(EE / 4 + 255) / 256, 256>>>(src, dst, rowptr, cnt, csr_src, ea, S);

    // ---- 3 fused layers: gather + mini-GEMM in one kernel ----
    fused_layer<<<FB, 256>>>(x, csr_src, rowptr, S, Wn + 0 * 4096, We + 0 * 320,
                             bp + 0 * 64, h1, 0);
    fused_layer<<<FB, 256>>>(h1, csr_src, rowptr, S, Wn + 1 * 4096, We + 1 * 320,
                             bp + 1 * 64, h2, 1);
    fused_layer<<<FB, 256>>>(h2, csr_src, rowptr, S, Wn + 2 * 4096, We + 2 * 320,
                             bp + 2 * 64, h3, 1);

    // ---- GAT tail ----
    attn_kernel<<<NB, 256>>>(h3, avec, asrc, adst);
    gat_agg_kernel<<<NB, 256>>>(csr_src, rowptr, (const float2*)asrc, (const float2*)adst,
                                h3, z);
    gemm_fin<<<(NN + 255) / 256, 256>>>(z, Wstk, b_gat, out, NN);
}

// round 11
// speedup vs baseline: 1.4447x; 1.0167x over previous
#include <cuda_runtime.h>

#define NN 100000
#define EE 800000
#define SCAN_CHUNK 1024
#define SCAN_NB 98   // 98*1024 = 100352 >= NN

typedef unsigned long long ull;

// ---------------- scratch (device globals) ----------------
__device__ float g_h1[NN * 64];
__device__ float g_h2[NN * 64];
__device__ float g_h3[NN * 64];
__device__ float g_z[NN * 128];
__device__ float g_asrc[NN * 2];
__device__ float g_adst[NN * 2];
__device__ float g_Wn[3][4096];
__device__ float g_We[3][320];
__device__ float g_bp[3][64];
__device__ float g_Wstk[8192];     // [k][c]: k<64 -> Wg[k][c] ; k>=64 -> Wg[k-64][64+c]
__device__ float g_avec[256];      // avS0[64] avS1[64] avD0[64] avD1[64]  (Wg @ att vectors)
__device__ int g_cnt[NN];
__device__ int g_rowptr[NN + 4];
__device__ int g_csr_src[EE];
__device__ float g_S[NN * 5];
__device__ int g_bsum[SCAN_NB];
__device__ int g_boff[SCAN_NB];

__device__ __forceinline__ float lrelu(float x) { return x > 0.f ? x : 0.2f * x; }

// f32x2 packed math (Blackwell): 2 fp32 FMAs per issue slot
__device__ __forceinline__ ull pk2(float x) {
    ull r; asm("mov.b64 %0,{%1,%1};" : "=l"(r) : "f"(x)); return r;
}
__device__ __forceinline__ void fma2(ull& d, ull a, ull b) {
    asm("fma.rn.f32x2 %0,%1,%2,%0;" : "+l"(d) : "l"(a), "l"(b));
}
__device__ __forceinline__ float2 up2(ull v) {
    float2 r; asm("mov.b64 {%0,%1},%2;" : "=f"(r.x), "=f"(r.y) : "l"(v)); return r;
}

// ---------------- weight folding (3 edge-conv layers + GAT weights) ----------------
struct FoldW { const float* w[18]; const float* wg; const float* as; const float* ad; };

__global__ void fold_kernel(FoldW fw, float* __restrict__ Wn, float* __restrict__ We,
                            float* __restrict__ bp, float* __restrict__ Wstk,
                            float* __restrict__ avec) {
    int L = blockIdx.y;
    int t = blockIdx.x * 256 + threadIdx.x;
    if (L < 3) {
        if (t >= 4480) return;
        const float* wn = fw.w[6 * L + 0];
        const float* bn = fw.w[6 * L + 1];
        const float* we = fw.w[6 * L + 2];
        const float* be = fw.w[6 * L + 3];
        const float* wc = fw.w[6 * L + 4];
        const float* bc = fw.w[6 * L + 5];
        if (t < 4096) {
            int r = t >> 6, c = t & 63;
            float s = 0.f;
            #pragma unroll 8
            for (int k = 0; k < 64; k++) s += wn[r * 64 + k] * wc[k * 64 + c];
            Wn[L * 4096 + t] = s;
        } else if (t < 4416) {
            int u = t - 4096;
            int j = u >> 6, c = u & 63;
            float s = 0.f;
            #pragma unroll 8
            for (int k = 0; k < 64; k++) s += we[j * 64 + k] * wc[(64 + k) * 64 + c];
            We[L * 320 + u] = s;
        } else {
            int c = t - 4416;
            float s = bc[c];
            #pragma unroll 8
            for (int k = 0; k < 64; k++)
                s += bn[k] * wc[k * 64 + c] + be[k] * wc[(64 + k) * 64 + c];
            bp[L * 64 + c] = s;
        }
    } else {
        if (t < 8192) {
            int k = t >> 6, c = t & 63;
            Wstk[t] = (k < 64) ? fw.wg[k * 128 + c] : fw.wg[(k - 64) * 128 + 64 + c];
        } else if (t < 8448) {
            int u = t - 8192;          // 0..255
            int vec = u >> 6;          // 0:avS0 1:avS1 2:avD0 3:avD1
            int k = u & 63;
            int hd = vec & 1;
            const float* att = (vec < 2) ? fw.as : fw.ad;
            float s = 0.f;
            #pragma unroll 8
            for (int c = 0; c < 64; c++) s += fw.wg[k * 128 + hd * 64 + c] * att[hd * 64 + c];
            avec[u] = s;
        }
    }
}

// ---------------- zero fill ----------------
__global__ void zero4_kernel(float4* __restrict__ p, int n4) {
    float4 z = make_float4(0.f, 0.f, 0.f, 0.f);
    for (int i = blockIdx.x * blockDim.x + threadIdx.x; i < n4; i += gridDim.x * blockDim.x)
        p[i] = z;
}

// ---------------- CSR build ----------------
__global__ void count_kernel(const int* __restrict__ dst, int* __restrict__ cnt) {
    int i = blockIdx.x * blockDim.x + threadIdx.x;
    if (i * 4 >= EE) return;
    int4 d = ((const int4*)dst)[i];
    atomicAdd(&cnt[d.x], 1);
    atomicAdd(&cnt[d.y], 1);
    atomicAdd(&cnt[d.z], 1);
    atomicAdd(&cnt[d.w], 1);
}

__global__ void scan_part(const int* __restrict__ cnt, int* __restrict__ bsum) {
    __shared__ int wsum[8];
    int b = blockIdx.x, t = threadIdx.x;
    int lane = t & 31, wid = t >> 5;
    int idx = b * SCAN_CHUNK + t * 4;
    int s = 0;
    if (idx < NN) {
        int4 v = *(const int4*)(cnt + idx);
        s = v.x + v.y + v.z + v.w;
    }
    #pragma unroll
    for (int o = 16; o; o >>= 1) s += __shfl_xor_sync(0xffffffffu, s, o);
    if (lane == 0) wsum[wid] = s;
    __syncthreads();
    if (t == 0) {
        int tot = 0;
        #pragma unroll
        for (int w = 0; w < 8; w++) tot += wsum[w];
        bsum[b] = tot;
    }
}

__global__ void scan_top(const int* __restrict__ bsum, int* __restrict__ boff) {
    __shared__ int wtot[4];
    int t = threadIdx.x;           // 128 threads
    int lane = t & 31, wid = t >> 5;
    int v = (t < SCAN_NB) ? bsum[t] : 0;
    int incl = v;
    #pragma unroll
    for (int o = 1; o < 32; o <<= 1) {
        int u = __shfl_up_sync(0xffffffffu, incl, o);
        if (lane >= o) incl += u;
    }
    if (lane == 31) wtot[wid] = incl;
    __syncthreads();
    int woff = 0;
    for (int w = 0; w < wid; w++) woff += wtot[w];
    if (t < SCAN_NB) boff[t] = woff + incl - v;
}

__global__ void scan_final(const int* __restrict__ cnt, const int* __restrict__ boff,
                           int* __restrict__ rowptr) {
    __shared__ int wsum[8];
    int b = blockIdx.x, t = threadIdx.x;
    int lane = t & 31, wid = t >> 5;
    int idx = b * SCAN_CHUNK + t * 4;
    int v[4] = {0, 0, 0, 0};
    if (idx < NN) {
        int4 d = *(const int4*)(cnt + idx);
        v[0] = d.x; v[1] = d.y; v[2] = d.z; v[3] = d.w;
    }
    #pragma unroll
    for (int j = 1; j < 4; j++) v[j] += v[j - 1];
    int tot = v[3];
    int incl = tot;
    #pragma unroll
    for (int o = 1; o < 32; o <<= 1) {
        int u = __shfl_up_sync(0xffffffffu, incl, o);
        if (lane >= o) incl += u;
    }
    if (lane == 31) wsum[wid] = incl;
    __syncthreads();
    int woff = 0;
    for (int w = 0; w < wid; w++) woff += wsum[w];
    int excl = boff[b] + woff + incl - tot;
    if (idx < NN) {
        #pragma unroll
        for (int j = 0; j < 4; j++) rowptr[idx + j + 1] = excl + v[j];
    }
    if (b == 0 && t == 0) rowptr[0] = 0;
}

__device__ __forceinline__ void scat1(int d, int s, int e, const int* __restrict__ rowptr,
                                      int* __restrict__ cnt, int* __restrict__ csr_src,
                                      const float* __restrict__ ea, float* __restrict__ S) {
    int pos = atomicAdd(&cnt[d], -1) - 1;
    csr_src[rowptr[d] + pos] = s;
    const float* eap = ea + (size_t)e * 5;
    #pragma unroll
    for (int k = 0; k < 5; k++) atomicAdd(&S[d * 5 + k], eap[k]);
}

__global__ void scatter_kernel(const int* __restrict__ src, const int* __restrict__ dst,
                               const int* __restrict__ rowptr, int* __restrict__ cnt,
                               int* __restrict__ csr_src, const float* __restrict__ ea,
                               float* __restrict__ S) {
    int i = blockIdx.x * blockDim.x + threadIdx.x;
    if (i * 4 >= EE) return;
    int4 d4 = ((const int4*)dst)[i];
    int4 s4 = ((const int4*)src)[i];
    int e = i * 4;
    scat1(d4.x, s4.x, e + 0, rowptr, cnt, csr_src, ea, S);
    scat1(d4.y, s4.y, e + 1, rowptr, cnt, csr_src, ea, S);
    scat1(d4.z, s4.z, e + 2, rowptr, cnt, csr_src, ea, S);
    scat1(d4.w, s4.w, e + 3, rowptr, cnt, csr_src, ea, S);
}

// ---------------- fused layer: gather 64 nodes -> smem qT -> block mini-GEMM ----------------
// out[n] = (Σ_src relu?(hin[src])) @ Wn + S[n] @ We + deg(n)*bp      [stored pre-relu]
// attn: epilogue computes aS/aD[n][hd] = relu(out[n]) . avec  (per-row dot, tcol reduce)
__global__ __launch_bounds__(256) void fused_layer(
    const float* __restrict__ hin, const int* __restrict__ csr_src,
    const int* __restrict__ rowptr, const float* __restrict__ S,
    const float* __restrict__ Wn, const float* __restrict__ We,
    const float* __restrict__ bp, float* __restrict__ out, int relu,
    int attn, const float* __restrict__ avec,
    float* __restrict__ aS, float* __restrict__ aD) {
    __shared__ float qT[70][68];   // row stride 272B
    __shared__ float Ws[70][64];
    __shared__ float sAv[256];
    int t = threadIdx.x;
    int n0 = blockIdx.x << 6;

    // load weights (70 rows x 64)
    #pragma unroll
    for (int i = 0; i < 5; i++) {
        int idx = t + i * 256;
        if (idx < 1120) {
            int r = idx >> 4, c4 = (idx & 15) << 2;
            float4 v;
            if (r < 64) v = *(const float4*)(Wn + r * 64 + c4);
            else if (r < 69) v = *(const float4*)(We + (r - 64) * 64 + c4);
            else v = *(const float4*)(bp + c4);
            *(float4*)&Ws[r][c4] = v;
        }
    }
    if (attn) sAv[t] = avec[t];

    // phase 1: each warp gathers 8 nodes (4-edge unrolled for MLP)
    int w = t >> 5, lane = t & 31;
    #pragma unroll
    for (int i = 0; i < 8; i++) {
        int nl = w * 8 + i;
        int n = n0 + nl;
        float q0 = 0.f, q1 = 0.f, deg = 0.f, sv = 0.f;
        if (n < NN) {
            int start = rowptr[n], end = rowptr[n + 1];
            deg = (float)(end - start);
            int j = start;
            for (; j + 3 < end; j += 4) {
                const float* pa = hin + (size_t)csr_src[j] * 64;
                const float* pb = hin + (size_t)csr_src[j + 1] * 64;
                const float* pc = hin + (size_t)csr_src[j + 2] * 64;
                const float* pd = hin + (size_t)csr_src[j + 3] * 64;
                float a0 = pa[lane], a1 = pa[lane + 32];
                float b0 = pb[lane], b1 = pb[lane + 32];
                float c0v = pc[lane], c1 = pc[lane + 32];
                float d0 = pd[lane], d1 = pd[lane + 32];
                if (relu) {
                    a0 = fmaxf(a0, 0.f); a1 = fmaxf(a1, 0.f);
                    b0 = fmaxf(b0, 0.f); b1 = fmaxf(b1, 0.f);
                    c0v = fmaxf(c0v, 0.f); c1 = fmaxf(c1, 0.f);
                    d0 = fmaxf(d0, 0.f); d1 = fmaxf(d1, 0.f);
                }
                q0 += (a0 + b0) + (c0v + d0);
                q1 += (a1 + b1) + (c1 + d1);
            }
            for (; j < end; j++) {
                const float* pa = hin + (size_t)csr_src[j] * 64;
                float a0 = pa[lane], a1 = pa[lane + 32];
                if (relu) { a0 = fmaxf(a0, 0.f); a1 = fmaxf(a1, 0.f); }
                q0 += a0;
                q1 += a1;
            }
            if (lane < 5) sv = S[(size_t)n * 5 + lane];
        }
        qT[lane][nl] = q0;
        qT[lane + 32][nl] = q1;
        if (lane < 5) qT[64 + lane][nl] = sv;
        if (lane == 5) qT[69][nl] = deg;
    }
    __syncthreads();

    // phase 2: 64x64 output, 70-deep, thread tile 4 rows x 4 cols
    int tcol = t & 15, trow = t >> 4;
    int r0 = trow << 2, c0 = tcol << 2;
    ull acc[4][2];
    #pragma unroll
    for (int i = 0; i < 4; i++) { acc[i][0] = 0ull; acc[i][1] = 0ull; }

    #pragma unroll 10
    for (int k = 0; k < 70; k++) {
        float4 a = *(float4*)&qT[k][r0];
        const ull* bb = (const ull*)&Ws[k][c0];
        ull b0 = bb[0], b1 = bb[1];
        ull a0 = pk2(a.x), a1 = pk2(a.y), a2 = pk2(a.z), a3 = pk2(a.w);
        fma2(acc[0][0], a0, b0); fma2(acc[0][1], a0, b1);
        fma2(acc[1][0], a1, b0); fma2(acc[1][1], a1, b1);
        fma2(acc[2][0], a2, b0); fma2(acc[2][1], a2, b1);
        fma2(acc[3][0], a3, b0); fma2(acc[3][1], a3, b1);
    }

    #pragma unroll
    for (int i = 0; i < 4; i++) {
        int n = n0 + r0 + i;
        float2 p0 = up2(acc[i][0]), p1 = up2(acc[i][1]);
        if (n < NN)
            *(float4*)(out + (size_t)n * 64 + c0) = make_float4(p0.x, p0.y, p1.x, p1.y);
        if (attn) {
            // per-row attn dots: relu(out) . avec, reduce across 16 tcol lanes
            float r0v = fmaxf(p0.x, 0.f), r1v = fmaxf(p0.y, 0.f);
            float r2v = fmaxf(p1.x, 0.f), r3v = fmaxf(p1.y, 0.f);
            float pS0 = r0v * sAv[c0] + r1v * sAv[c0 + 1] + r2v * sAv[c0 + 2] + r3v * sAv[c0 + 3];
            float pS1 = r0v * sAv[64 + c0] + r1v * sAv[64 + c0 + 1] + r2v * sAv[64 + c0 + 2] + r3v * sAv[64 + c0 + 3];
            float pD0 = r0v * sAv[128 + c0] + r1v * sAv[128 + c0 + 1] + r2v * sAv[128 + c0 + 2] + r3v * sAv[128 + c0 + 3];
            float pD1 = r0v * sAv[192 + c0] + r1v * sAv[192 + c0 + 1] + r2v * sAv[192 + c0 + 2] + r3v * sAv[192 + c0 + 3];
            #pragma unroll
            for (int o = 1; o < 16; o <<= 1) {
                pS0 += __shfl_xor_sync(0xffffffffu, pS0, o);
                pS1 += __shfl_xor_sync(0xffffffffu, pS1, o);
                pD0 += __shfl_xor_sync(0xffffffffu, pD0, o);
                pD1 += __shfl_xor_sync(0xffffffffu, pD1, o);
            }
            if (tcol == 0 && n < NN) {
                aS[n * 2] = pS0; aS[n * 2 + 1] = pS1;
                aD[n * 2] = pD0; aD[n * 2 + 1] = pD1;
            }
        }
    }
}

// ---------------- GAT aggregation: softmax-weighted sum of relu(h3) rows -> z[N,128] ----------------
__global__ void gat_agg_kernel(const int* __restrict__ csr_src, const int* __restrict__ rowptr,
                               const float2* __restrict__ aS, const float2* __restrict__ aD,
                               const float* __restrict__ h, float* __restrict__ z) {
    int n = blockIdx.x * 8 + (threadIdx.x >> 5);
    int lane = threadIdx.x & 31;
    int start = rowptr[n], end = rowptr[n + 1];
    float2 ad = aD[n];

    // pass 1: lane-parallel segment max (also warms L1 with aS lines)
    float m0 = -1e30f, m1 = -1e30f;
    for (int j = start + lane; j < end; j += 32) {
        float2 as = aS[csr_src[j]];
        m0 = fmaxf(m0, lrelu(as.x + ad.x));
        m1 = fmaxf(m1, lrelu(as.y + ad.y));
    }
    #pragma unroll
    for (int o = 16; o; o >>= 1) {
        m0 = fmaxf(m0, __shfl_xor_sync(0xffffffffu, m0, o));
        m1 = fmaxf(m1, __shfl_xor_sync(0xffffffffu, m1, o));
    }

    // pass 2: serial, 2-edge unrolled; aS loads are L1-warm
    float acc0 = 0.f, acc1 = 0.f, acc2 = 0.f, acc3 = 0.f, den0 = 0.f, den1 = 0.f;
    int j = start;
    for (; j + 1 < end; j += 2) {
        int sA = csr_src[j], sB = csr_src[j + 1];
        float2 aA = aS[sA], aB = aS[sB];
        const float* hA = h + (size_t)sA * 64;
        const float* hB = h + (size_t)sB * 64;
        float vA0 = fmaxf(hA[lane], 0.f), vA1 = fmaxf(hA[lane + 32], 0.f);
        float vB0 = fmaxf(hB[lane], 0.f), vB1 = fmaxf(hB[lane + 32], 0.f);
        float wA0 = __expf(lrelu(aA.x + ad.x) - m0);
        float wA1 = __expf(lrelu(aA.y + ad.y) - m1);
        float wB0 = __expf(lrelu(aB.x + ad.x) - m0);
        float wB1 = __expf(lrelu(aB.y + ad.y) - m1);
        den0 += wA0 + wB0;
        den1 += wA1 + wB1;
        acc0 += wA0 * vA0 + wB0 * vB0;
        acc1 += wA0 * vA1 + wB0 * vB1;
        acc2 += wA1 * vA0 + wB1 * vB0;
        acc3 += wA1 * vA1 + wB1 * vB1;
    }
    if (j < end) {
        int sA = csr_src[j];
        float2 aA = aS[sA];
        const float* hA = h + (size_t)sA * 64;
        float vA0 = fmaxf(hA[lane], 0.f), vA1 = fmaxf(hA[lane + 32], 0.f);
        float wA0 = __expf(lrelu(aA.x + ad.x) - m0);
        float wA1 = __expf(lrelu(aA.y + ad.y) - m1);
        den0 += wA0;
        den1 += wA1;
        acc0 += wA0 * vA0;
        acc1 += wA0 * vA1;
        acc2 += wA1 * vA0;
        acc3 += wA1 * vA1;
    }
    float id0 = 0.5f / (den0 + 1e-16f);
    float id1 = 0.5f / (den1 + 1e-16f);
    float* zn = z + (size_t)n * 128;
    zn[lane]      = acc0 * id0;
    zn[lane + 32] = acc1 * id0;
    zn[lane + 64] = acc2 * id1;
    zn[lane + 96] = acc3 * id1;
}

// ---------------- final GEMM: out = z[N,128] @ Wstk[128,64] + b_gat ----------------
__global__ __launch_bounds__(256) void gemm_fin(
    const float* __restrict__ z, const float* __restrict__ Wstk,
    const float* __restrict__ bias, float* __restrict__ out, int n) {
    __shared__ float Ws[128][64];   // 32KB
    int n0 = blockIdx.x << 8;
    int t = threadIdx.x;
    int tx = t & 7, ty = t >> 3;

    #pragma unroll
    for (int i = 0; i < 8; i++) {
        int idx = t + i * 256;
        int k = idx >> 4;
        int c4 = (idx & 15) << 2;
        *(float4*)&Ws[k][c4] = *(const float4*)(Wstk + k * 64 + c4);
    }
    __syncthreads();

    int r0 = n0 + ty * 8;
    ull acc[8][4];
    #pragma unroll
    for (int i = 0; i < 8; i++)
        #pragma unroll
        for (int j = 0; j < 4; j++) acc[i][j] = 0ull;

    for (int kc = 0; kc < 128; kc += 4) {
        float4 a[8];
        #pragma unroll
        for (int i = 0; i < 8; i++) {
            int row = r0 + i;
            a[i] = (row < n) ? *(const float4*)(z + (size_t)row * 128 + kc)
                             : make_float4(0.f, 0.f, 0.f, 0.f);
        }
        #pragma unroll
        for (int kk = 0; kk < 4; kk++) {
            const ull* bb = (const ull*)&Ws[kc + kk][tx * 8];
            ull b0 = bb[0], b1 = bb[1], b2 = bb[2], b3 = bb[3];
            #pragma unroll
            for (int i = 0; i < 8; i++) {
                float av = (kk == 0) ? a[i].x : (kk == 1) ? a[i].y : (kk == 2) ? a[i].z : a[i].w;
                ull a2 = pk2(av);
                fma2(acc[i][0], a2, b0);
                fma2(acc[i][1], a2, b1);
                fma2(acc[i][2], a2, b2);
                fma2(acc[i][3], a2, b3);
            }
        }
    }

    float4 bA = *(const float4*)(bias + tx * 8);
    float4 bB = *(const float4*)(bias + tx * 8 + 4);
    #pragma unroll
    for (int i = 0; i < 8; i++) {
        int row = r0 + i;
        if (row < n) {
            float2 p0 = up2(acc[i][0]), p1 = up2(acc[i][1]);
            float2 p2 = up2(acc[i][2]), p3 = up2(acc[i][3]);
            *(float4*)(out + (size_t)row * 64 + tx * 8) =
                make_float4(p0.x + bA.x, p0.y + bA.y, p1.x + bA.z, p1.y + bA.w);
            *(float4*)(out + (size_t)row * 64 + tx * 8 + 4) =
                make_float4(p2.x + bB.x, p2.y + bB.y, p3.x + bB.z, p3.y + bB.w);
        }
    }
}

// ---------------- launch ----------------
extern "C" void kernel_launch(void* const* d_in, const int* in_sizes, int n_in,
                              void* d_out, int out_size) {
    const float* x = (const float*)d_in[0];
    const int* ei = (const int*)d_in[1];
    const float* ea = (const float*)d_in[2];
    const int* src = ei;
    const int* dst = ei + EE;
    FoldW fw;
    for (int i = 0; i < 18; i++) fw.w[i] = (const float*)d_in[3 + i];
    fw.wg = (const float*)d_in[21];
    fw.as = (const float*)d_in[22];
    fw.ad = (const float*)d_in[23];
    const float* b_gat = (const float*)d_in[24];
    float* out = (float*)d_out;

    float *h1, *h2, *h3, *z, *asrc, *adst, *Wn, *We, *bp, *Wstk, *avec, *S;
    int *cnt, *rowptr, *csr_src, *bsum, *boff;
    cudaGetSymbolAddress((void**)&h1, g_h1);
    cudaGetSymbolAddress((void**)&h2, g_h2);
    cudaGetSymbolAddress((void**)&h3, g_h3);
    cudaGetSymbolAddress((void**)&z, g_z);
    cudaGetSymbolAddress((void**)&asrc, g_asrc);
    cudaGetSymbolAddress((void**)&adst, g_adst);
    cudaGetSymbolAddress((void**)&Wn, g_Wn);
    cudaGetSymbolAddress((void**)&We, g_We);
    cudaGetSymbolAddress((void**)&bp, g_bp);
    cudaGetSymbolAddress((void**)&Wstk, g_Wstk);
    cudaGetSymbolAddress((void**)&avec, g_avec);
    cudaGetSymbolAddress((void**)&cnt, g_cnt);
    cudaGetSymbolAddress((void**)&rowptr, g_rowptr);
    cudaGetSymbolAddress((void**)&csr_src, g_csr_src);
    cudaGetSymbolAddress((void**)&S, g_S);
    cudaGetSymbolAddress((void**)&bsum, g_bsum);
    cudaGetSymbolAddress((void**)&boff, g_boff);

    const int NB = NN / 8;                 // 12500 warp-per-node blocks
    const int FB = (NN + 63) / 64;         // 1563 fused-layer blocks

    // ---- CSR build + weight folding ----
    zero4_kernel<<<98, 256>>>((float4*)cnt, NN / 4);
    count_kernel<<<(EE / 4 + 255) / 256, 256>>>(dst, cnt);
    scan_part<<<SCAN_NB, 256>>>(cnt, bsum);
    scan_top<<<1, 128>>>(bsum, boff);
    fold_kernel<<<dim3(33, 4), 256>>>(fw, Wn, We, bp, Wstk, avec);
    scan_final<<<SCAN_NB, 256>>>(cnt, boff, rowptr);
    zero4_kernel<<<489, 256>>>((float4*)S, NN * 5 / 4);
    scatter_kernel<<<(EE / 4 + 255) / 256, 256>>>(src, dst, rowptr, cnt, csr_src, ea, S);

    // ---- 3 fused layers: gather + mini-GEMM (+ attn epilogue on L3) ----
    fused_layer<<<FB, 256>>>(x, csr_src, rowptr, S, Wn + 0 * 4096, We + 0 * 320,
                             bp + 0 * 64, h1, 0, 0, avec, nullptr, nullptr);
    fused_layer<<<FB, 256>>>(h1, csr_src, rowptr, S, Wn + 1 * 4096, We + 1 * 320,
                             bp + 1 * 64, h2, 1, 0, avec, nullptr, nullptr);
    fused_layer<<<FB, 256>>>(h2, csr_src, rowptr, S, Wn + 2 * 4096, We + 2 * 320,
                             bp + 2 * 64, h3, 1, 1, avec, asrc, adst);

    // ---- GAT tail ----
    gat_agg_kernel<<<NB, 256>>>(csr_src, rowptr, (const float2*)asrc, (const float2*)adst,
                                h3, z);
    gemm_fin<<<(NN + 255) / 256, 256>>>(z, Wstk, b_gat, out, NN);
}

// round 12
// speedup vs baseline: 1.4980x; 1.0370x over previous
#include <cuda_runtime.h>

#define NN 100000
#define EE 800000
#define SCAN_NB 98   // 98*1024 = 100352 >= NN

typedef unsigned long long ull;

// ---------------- scratch (device globals) ----------------
__device__ float g_h1[NN * 64];
__device__ float g_h2[NN * 64];
__device__ float g_h3[NN * 64];
__device__ float g_asrc[NN * 2];
__device__ float g_adst[NN * 2];
__device__ float g_Wn[3][4096];
__device__ float g_We[3][320];
__device__ float g_bp[3][64];
__device__ float g_Wstk[8192];     // [k][c]: k<64 -> Wg[k][c] ; k>=64 -> Wg[k-64][64+c]
__device__ float g_avec[256];      // avS0[64] avS1[64] avD0[64] avD1[64]
__device__ int g_cnt[NN];
__device__ int g_rowptr[NN + 4];
__device__ int g_csr_src[EE];
__device__ float g_S[NN * 5];
__device__ int g_scanflag[SCAN_NB];   // 0 = not ready; else block_total + 1

__device__ __forceinline__ float lrelu(float x) { return x > 0.f ? x : 0.2f * x; }

__device__ __forceinline__ ull pk2(float x) {
    ull r; asm("mov.b64 %0,{%1,%1};" : "=l"(r) : "f"(x)); return r;
}
__device__ __forceinline__ void fma2(ull& d, ull a, ull b) {
    asm("fma.rn.f32x2 %0,%1,%2,%0;" : "+l"(d) : "l"(a), "l"(b));
}
__device__ __forceinline__ float2 up2(ull v) {
    float2 r; asm("mov.b64 {%0,%1},%2;" : "=f"(r.x), "=f"(r.y) : "l"(v)); return r;
}

// ---------------- zero all scratch that must be reset each call ----------------
__global__ void zero_all(int4* __restrict__ cnt4, float4* __restrict__ S4,
                         int* __restrict__ flag) {
    int i = blockIdx.x * blockDim.x + threadIdx.x;
    if (i < NN / 4) cnt4[i] = make_int4(0, 0, 0, 0);
    if (i < NN * 5 / 4) S4[i] = make_float4(0.f, 0.f, 0.f, 0.f);
    if (i < SCAN_NB) flag[i] = 0;
}

// ---------------- count (blocks 0..781) + weight fold (blocks 782..913) ----------------
struct FoldW { const float* w[18]; const float* wg; const float* as; const float* ad; };

__global__ void count_fold(const int* __restrict__ dst, int* __restrict__ cnt,
                           FoldW fw, float* __restrict__ Wn, float* __restrict__ We,
                           float* __restrict__ bp, float* __restrict__ Wstk,
                           float* __restrict__ avec) {
    int b = blockIdx.x;
    if (b < 782) {
        int i = b * 256 + threadIdx.x;
        if (i * 4 >= EE) return;
        int4 d = ((const int4*)dst)[i];
        atomicAdd(&cnt[d.x], 1);
        atomicAdd(&cnt[d.y], 1);
        atomicAdd(&cnt[d.z], 1);
        atomicAdd(&cnt[d.w], 1);
        return;
    }
    int fb = b - 782;
    int L = fb / 33;
    int t = (fb % 33) * 256 + threadIdx.x;
    if (L < 3) {
        if (t >= 4480) return;
        const float* wn = fw.w[6 * L + 0];
        const float* bn = fw.w[6 * L + 1];
        const float* we = fw.w[6 * L + 2];
        const float* be = fw.w[6 * L + 3];
        const float* wc = fw.w[6 * L + 4];
        const float* bc = fw.w[6 * L + 5];
        if (t < 4096) {
            int r = t >> 6, c = t & 63;
            float s = 0.f;
            #pragma unroll 8
            for (int k = 0; k < 64; k++) s += wn[r * 64 + k] * wc[k * 64 + c];
            Wn[L * 4096 + t] = s;
        } else if (t < 4416) {
            int u = t - 4096;
            int j = u >> 6, c = u & 63;
            float s = 0.f;
            #pragma unroll 8
            for (int k = 0; k < 64; k++) s += we[j * 64 + k] * wc[(64 + k) * 64 + c];
            We[L * 320 + u] = s;
        } else {
            int c = t - 4416;
            float s = bc[c];
            #pragma unroll 8
            for (int k = 0; k < 64; k++)
                s += bn[k] * wc[k * 64 + c] + be[k] * wc[(64 + k) * 64 + c];
            bp[L * 64 + c] = s;
        }
    } else {
        if (t < 8192) {
            int k = t >> 6, c = t & 63;
            Wstk[t] = (k < 64) ? fw.wg[k * 128 + c] : fw.wg[(k - 64) * 128 + 64 + c];
        } else if (t < 8448) {
            int u = t - 8192;
            int vec = u >> 6;
            int k = u & 63;
            int hd = vec & 1;
            const float* att = (vec < 2) ? fw.as : fw.ad;
            float s = 0.f;
            #pragma unroll 8
            for (int c = 0; c < 64; c++) s += fw.wg[k * 128 + hd * 64 + c] * att[hd * 64 + c];
            avec[u] = s;
        }
    }
}

// ---------------- single-kernel scan (all 98 blocks resident; flag = total+1) ----------------
__global__ void scan_lb(const int* __restrict__ cnt, int* __restrict__ flag,
                        int* __restrict__ rowptr) {
    __shared__ int wsum[8];
    __shared__ int offsum[8];
    __shared__ int s_boff;
    int b = blockIdx.x, t = threadIdx.x;
    int lane = t & 31, wid = t >> 5;
    int idx = b * 1024 + t * 4;
    int v[4] = {0, 0, 0, 0};
    if (idx < NN) {                 // NN % 4 == 0 -> full int4 or none
        int4 d = *(const int4*)(cnt + idx);
        v[0] = d.x; v[1] = d.y; v[2] = d.z; v[3] = d.w;
    }
    #pragma unroll
    for (int j = 1; j < 4; j++) v[j] += v[j - 1];
    int tot = v[3];
    int incl = tot;
    #pragma unroll
    for (int o = 1; o < 32; o <<= 1) {
        int u = __shfl_up_sync(0xffffffffu, incl, o);
        if (lane >= o) incl += u;
    }
    if (lane == 31) wsum[wid] = incl;
    __syncthreads();
    // block total & publish
    if (t == 0) {
        int bt = 0;
        #pragma unroll
        for (int w = 0; w < 8; w++) bt += wsum[w];
        atomicExch(&flag[b], bt + 1);
    }
    // block offset: thread p polls predecessor p
    int agg = 0;
    if (t < b) {
        volatile int* vf = (volatile int*)flag;
        int val;
        do { val = vf[t]; } while (val == 0);
        agg = val - 1;
    }
    #pragma unroll
    for (int o = 16; o; o >>= 1) agg += __shfl_xor_sync(0xffffffffu, agg, o);
    if (lane == 0) offsum[wid] = agg;
    __syncthreads();
    if (t == 0) {
        int bo = 0;
        #pragma unroll
        for (int w = 0; w < 8; w++) bo += offsum[w];
        s_boff = bo;
    }
    __syncthreads();
    int woff = 0;
    for (int w = 0; w < wid; w++) woff += wsum[w];
    int excl = s_boff + woff + incl - tot;
    if (idx < NN) {
        #pragma unroll
        for (int j = 0; j < 4; j++) rowptr[idx + j + 1] = excl + v[j];
    }
    if (b == 0 && t == 0) rowptr[0] = 0;
}

// ---------------- scatter: countdown on cnt, fused S accumulation ----------------
__device__ __forceinline__ void scat1(int d, int s, int e, const int* __restrict__ rowptr,
                                      int* __restrict__ cnt, int* __restrict__ csr_src,
                                      const float* __restrict__ ea, float* __restrict__ S) {
    int pos = atomicAdd(&cnt[d], -1) - 1;
    csr_src[rowptr[d] + pos] = s;
    const float* eap = ea + (size_t)e * 5;
    #pragma unroll
    for (int k = 0; k < 5; k++) atomicAdd(&S[d * 5 + k], eap[k]);
}

__global__ void scatter_kernel(const int* __restrict__ src, const int* __restrict__ dst,
                               const int* __restrict__ rowptr, int* __restrict__ cnt,
                               int* __restrict__ csr_src, const float* __restrict__ ea,
                               float* __restrict__ S) {
    int i = blockIdx.x * blockDim.x + threadIdx.x;
    if (i * 4 >= EE) return;
    int4 d4 = ((const int4*)dst)[i];
    int4 s4 = ((const int4*)src)[i];
    int e = i * 4;
    scat1(d4.x, s4.x, e + 0, rowptr, cnt, csr_src, ea, S);
    scat1(d4.y, s4.y, e + 1, rowptr, cnt, csr_src, ea, S);
    scat1(d4.z, s4.z, e + 2, rowptr, cnt, csr_src, ea, S);
    scat1(d4.w, s4.w, e + 3, rowptr, cnt, csr_src, ea, S);
}

// ---------------- fused layer (unchanged from R11) ----------------
__global__ __launch_bounds__(256) void fused_layer(
    const float* __restrict__ hin, const int* __restrict__ csr_src,
    const int* __restrict__ rowptr, const float* __restrict__ S,
    const float* __restrict__ Wn, const float* __restrict__ We,
    const float* __restrict__ bp, float* __restrict__ out, int relu,
    int attn, const float* __restrict__ avec,
    float* __restrict__ aS, float* __restrict__ aD) {
    __shared__ float qT[70][68];
    __shared__ float Ws[70][64];
    __shared__ float sAv[256];
    int t = threadIdx.x;
    int n0 = blockIdx.x << 6;

    #pragma unroll
    for (int i = 0; i < 5; i++) {
        int idx = t + i * 256;
        if (idx < 1120) {
            int r = idx >> 4, c4 = (idx & 15) << 2;
            float4 v;
            if (r < 64) v = *(const float4*)(Wn + r * 64 + c4);
            else if (r < 69) v = *(const float4*)(We + (r - 64) * 64 + c4);
            else v = *(const float4*)(bp + c4);
            *(float4*)&Ws[r][c4] = v;
        }
    }
    if (attn) sAv[t] = avec[t];

    int w = t >> 5, lane = t & 31;
    #pragma unroll
    for (int i = 0; i < 8; i++) {
        int nl = w * 8 + i;
        int n = n0 + nl;
        float q0 = 0.f, q1 = 0.f, deg = 0.f, sv = 0.f;
        if (n < NN) {
            int start = rowptr[n], end = rowptr[n + 1];
            deg = (float)(end - start);
            int j = start;
            for (; j + 3 < end; j += 4) {
                const float* pa = hin + (size_t)csr_src[j] * 64;
                const float* pb = hin + (size_t)csr_src[j + 1] * 64;
                const float* pc = hin + (size_t)csr_src[j + 2] * 64;
                const float* pd = hin + (size_t)csr_src[j + 3] * 64;
                float a0 = pa[lane], a1 = pa[lane + 32];
                float b0 = pb[lane], b1 = pb[lane + 32];
                float c0v = pc[lane], c1 = pc[lane + 32];
                float d0 = pd[lane], d1 = pd[lane + 32];
                if (relu) {
                    a0 = fmaxf(a0, 0.f); a1 = fmaxf(a1, 0.f);
                    b0 = fmaxf(b0, 0.f); b1 = fmaxf(b1, 0.f);
                    c0v = fmaxf(c0v, 0.f); c1 = fmaxf(c1, 0.f);
                    d0 = fmaxf(d0, 0.f); d1 = fmaxf(d1, 0.f);
                }
                q0 += (a0 + b0) + (c0v + d0);
                q1 += (a1 + b1) + (c1 + d1);
            }
            for (; j < end; j++) {
                const float* pa = hin + (size_t)csr_src[j] * 64;
                float a0 = pa[lane], a1 = pa[lane + 32];
                if (relu) { a0 = fmaxf(a0, 0.f); a1 = fmaxf(a1, 0.f); }
                q0 += a0;
                q1 += a1;
            }
            if (lane < 5) sv = S[(size_t)n * 5 + lane];
        }
        qT[lane][nl] = q0;
        qT[lane + 32][nl] = q1;
        if (lane < 5) qT[64 + lane][nl] = sv;
        if (lane == 5) qT[69][nl] = deg;
    }
    __syncthreads();

    int tcol = t & 15, trow = t >> 4;
    int r0 = trow << 2, c0 = tcol << 2;
    ull acc[4][2];
    #pragma unroll
    for (int i = 0; i < 4; i++) { acc[i][0] = 0ull; acc[i][1] = 0ull; }

    #pragma unroll 10
    for (int k = 0; k < 70; k++) {
        float4 a = *(float4*)&qT[k][r0];
        const ull* bb = (const ull*)&Ws[k][c0];
        ull b0 = bb[0], b1 = bb[1];
        ull a0 = pk2(a.x), a1 = pk2(a.y), a2 = pk2(a.z), a3 = pk2(a.w);
        fma2(acc[0][0], a0, b0); fma2(acc[0][1], a0, b1);
        fma2(acc[1][0], a1, b0); fma2(acc[1][1], a1, b1);
        fma2(acc[2][0], a2, b0); fma2(acc[2][1], a2, b1);
        fma2(acc[3][0], a3, b0); fma2(acc[3][1], a3, b1);
    }

    #pragma unroll
    for (int i = 0; i < 4; i++) {
        int n = n0 + r0 + i;
        float2 p0 = up2(acc[i][0]), p1 = up2(acc[i][1]);
        if (n < NN)
            *(float4*)(out + (size_t)n * 64 + c0) = make_float4(p0.x, p0.y, p1.x, p1.y);
        if (attn) {
            float r0v = fmaxf(p0.x, 0.f), r1v = fmaxf(p0.y, 0.f);
            float r2v = fmaxf(p1.x, 0.f), r3v = fmaxf(p1.y, 0.f);
            float pS0 = r0v * sAv[c0] + r1v * sAv[c0 + 1] + r2v * sAv[c0 + 2] + r3v * sAv[c0 + 3];
            float pS1 = r0v * sAv[64 + c0] + r1v * sAv[64 + c0 + 1] + r2v * sAv[64 + c0 + 2] + r3v * sAv[64 + c0 + 3];
            float pD0 = r0v * sAv[128 + c0] + r1v * sAv[128 + c0 + 1] + r2v * sAv[128 + c0 + 2] + r3v * sAv[128 + c0 + 3];
            float pD1 = r0v * sAv[192 + c0] + r1v * sAv[192 + c0 + 1] + r2v * sAv[192 + c0 + 2] + r3v * sAv[192 + c0 + 3];
            #pragma unroll
            for (int o = 1; o < 16; o <<= 1) {
                pS0 += __shfl_xor_sync(0xffffffffu, pS0, o);
                pS1 += __shfl_xor_sync(0xffffffffu, pS1, o);
                pD0 += __shfl_xor_sync(0xffffffffu, pD0, o);
                pD1 += __shfl_xor_sync(0xffffffffu, pD1, o);
            }
            if (tcol == 0 && n < NN) {
                aS[n * 2] = pS0; aS[n * 2 + 1] = pS1;
                aD[n * 2] = pD0; aD[n * 2 + 1] = pD1;
            }
        }
    }
}

// ---------------- fused GAT: weighted gather -> smem zT -> mini-GEMM -> out ----------------
// dynamic smem: zT[128][68] (8704 floats) + Wc[64][64] (4096 floats) = 51200 B
__global__ __launch_bounds__(256) void gat_fused(
    const int* __restrict__ csr_src, const int* __restrict__ rowptr,
    const float2* __restrict__ aS, const float2* __restrict__ aD,
    const float* __restrict__ h, const float* __restrict__ Wstk,
    const float* __restrict__ bias, float* __restrict__ out) {
    extern __shared__ float sm[];
    float* zT = sm;            // [128][68]
    float* Wc = sm + 128 * 68; // [64][64]
    int t = threadIdx.x;
    int n0 = blockIdx.x << 6;

    // load weight chunk 0 (Wstk rows 0..63)
    #pragma unroll
    for (int i = 0; i < 4; i++) {
        int idx = t + i * 256;     // 1024 float4
        int r = idx >> 4, c4 = (idx & 15) << 2;
        *(float4*)&Wc[r * 64 + c4] = *(const float4*)(Wstk + r * 64 + c4);
    }

    // phase 1: each warp handles 8 nodes (softmax-weighted gather)
    int w = t >> 5, lane = t & 31;
    #pragma unroll
    for (int i = 0; i < 8; i++) {
        int nl = w * 8 + i;
        int n = n0 + nl;
        float acc0 = 0.f, acc1 = 0.f, acc2 = 0.f, acc3 = 0.f;
        float id0 = 0.f, id1 = 0.f;
        if (n < NN) {
            int start = rowptr[n], end = rowptr[n + 1];
            float2 ad = aD[n];
            // lane-parallel segment max (warms L1 with aS lines)
            float m0 = -1e30f, m1 = -1e30f;
            for (int j = start + lane; j < end; j += 32) {
                float2 as = aS[csr_src[j]];
                m0 = fmaxf(m0, lrelu(as.x + ad.x));
                m1 = fmaxf(m1, lrelu(as.y + ad.y));
            }
            #pragma unroll
            for (int o = 16; o; o >>= 1) {
                m0 = fmaxf(m0, __shfl_xor_sync(0xffffffffu, m0, o));
                m1 = fmaxf(m1, __shfl_xor_sync(0xffffffffu, m1, o));
            }
            float den0 = 0.f, den1 = 0.f;
            int j = start;
            for (; j + 1 < end; j += 2) {
                int sA = csr_src[j], sB = csr_src[j + 1];
                float2 aA = aS[sA], aB = aS[sB];
                const float* hA = h + (size_t)sA * 64;
                const float* hB = h + (size_t)sB * 64;
                float vA0 = fmaxf(hA[lane], 0.f), vA1 = fmaxf(hA[lane + 32], 0.f);
                float vB0 = fmaxf(hB[lane], 0.f), vB1 = fmaxf(hB[lane + 32], 0.f);
                float wA0 = __expf(lrelu(aA.x + ad.x) - m0);
                float wA1 = __expf(lrelu(aA.y + ad.y) - m1);
                float wB0 = __expf(lrelu(aB.x + ad.x) - m0);
                float wB1 = __expf(lrelu(aB.y + ad.y) - m1);
                den0 += wA0 + wB0;
                den1 += wA1 + wB1;
                acc0 += wA0 * vA0 + wB0 * vB0;
                acc1 += wA0 * vA1 + wB0 * vB1;
                acc2 += wA1 * vA0 + wB1 * vB0;
                acc3 += wA1 * vA1 + wB1 * vB1;
            }
            if (j < end) {
                int sA = csr_src[j];
                float2 aA = aS[sA];
                const float* hA = h + (size_t)sA * 64;
                float vA0 = fmaxf(hA[lane], 0.f), vA1 = fmaxf(hA[lane + 32], 0.f);
                float wA0 = __expf(lrelu(aA.x + ad.x) - m0);
                float wA1 = __expf(lrelu(aA.y + ad.y) - m1);
                den0 += wA0;
                den1 += wA1;
                acc0 += wA0 * vA0;
                acc1 += wA0 * vA1;
                acc2 += wA1 * vA0;
                acc3 += wA1 * vA1;
            }
            id0 = 0.5f / (den0 + 1e-16f);
            id1 = 0.5f / (den1 + 1e-16f);
        }
        zT[(size_t)lane * 68 + nl] = acc0 * id0;
        zT[(size_t)(lane + 32) * 68 + nl] = acc1 * id0;
        zT[(size_t)(lane + 64) * 68 + nl] = acc2 * id1;
        zT[(size_t)(lane + 96) * 68 + nl] = acc3 * id1;
    }
    __syncthreads();

    // phase 2: out = zT^T @ Wstk + bias, k chunked 2x64
    int tcol = t & 15, trow = t >> 4;
    int r0 = trow << 2, c0 = tcol << 2;
    ull acc[4][2];
    #pragma unroll
    for (int i = 0; i < 4; i++) { acc[i][0] = 0ull; acc[i][1] = 0ull; }

    #pragma unroll 8
    for (int k = 0; k < 64; k++) {
        float4 a = *(float4*)&zT[k * 68 + r0];
        const ull* bb = (const ull*)&Wc[k * 64 + c0];
        ull b0 = bb[0], b1 = bb[1];
        ull a0 = pk2(a.x), a1 = pk2(a.y), a2 = pk2(a.z), a3 = pk2(a.w);
        fma2(acc[0][0], a0, b0); fma2(acc[0][1], a0, b1);
        fma2(acc[1][0], a1, b0); fma2(acc[1][1], a1, b1);
        fma2(acc[2][0], a2, b0); fma2(acc[2][1], a2, b1);
        fma2(acc[3][0], a3, b0); fma2(acc[3][1], a3, b1);
    }
    __syncthreads();
    // load weight chunk 1 (Wstk rows 64..127)
    #pragma unroll
    for (int i = 0; i < 4; i++) {
        int idx = t + i * 256;
        int r = idx >> 4, c4 = (idx & 15) << 2;
        *(float4*)&Wc[r * 64 + c4] = *(const float4*)(Wstk + (64 + r) * 64 + c4);
    }
    __syncthreads();
    #pragma unroll 8
    for (int k = 0; k < 64; k++) {
        float4 a = *(float4*)&zT[(64 + k) * 68 + r0];
        const ull* bb = (const ull*)&Wc[k * 64 + c0];
        ull b0 = bb[0], b1 = bb[1];
        ull a0 = pk2(a.x), a1 = pk2(a.y), a2 = pk2(a.z), a3 = pk2(a.w);
        fma2(acc[0][0], a0, b0); fma2(acc[0][1], a0, b1);
        fma2(acc[1][0], a1, b0); fma2(acc[1][1], a1, b1);
        fma2(acc[2][0], a2, b0); fma2(acc[2][1], a2, b1);
        fma2(acc[3][0], a3, b0); fma2(acc[3][1], a3, b1);
    }

    float4 bv = *(const float4*)(bias + c0);
    #pragma unroll
    for (int i = 0; i < 4; i++) {
        int n = n0 + r0 + i;
        if (n < NN) {
            float2 p0 = up2(acc[i][0]), p1 = up2(acc[i][1]);
            *(float4*)(out + (size_t)n * 64 + c0) =
                make_float4(p0.x + bv.x, p0.y + bv.y, p1.x + bv.z, p1.y + bv.w);
        }
    }
}

// ---------------- launch ----------------
extern "C" void kernel_launch(void* const* d_in, const int* in_sizes, int n_in,
                              void* d_out, int out_size) {
    const float* x = (const float*)d_in[0];
    const int* ei = (const int*)d_in[1];
    const float* ea = (const float*)d_in[2];
    const int* src = ei;
    const int* dst = ei + EE;
    FoldW fw;
    for (int i = 0; i < 18; i++) fw.w[i] = (const float*)d_in[3 + i];
    fw.wg = (const float*)d_in[21];
    fw.as = (const float*)d_in[22];
    fw.ad = (const float*)d_in[23];
    const float* b_gat = (const float*)d_in[24];
    float* out = (float*)d_out;

    float *h1, *h2, *h3, *asrc, *adst, *Wn, *We, *bp, *Wstk, *avec, *S;
    int *cnt, *rowptr, *csr_src, *flag;
    cudaGetSymbolAddress((void**)&h1, g_h1);
    cudaGetSymbolAddress((void**)&h2, g_h2);
    cudaGetSymbolAddress((void**)&h3, g_h3);
    cudaGetSymbolAddress((void**)&asrc, g_asrc);
    cudaGetSymbolAddress((void**)&adst, g_adst);
    cudaGetSymbolAddress((void**)&Wn, g_Wn);
    cudaGetSymbolAddress((void**)&We, g_We);
    cudaGetSymbolAddress((void**)&bp, g_bp);
    cudaGetSymbolAddress((void**)&Wstk, g_Wstk);
    cudaGetSymbolAddress((void**)&avec, g_avec);
    cudaGetSymbolAddress((void**)&cnt, g_cnt);
    cudaGetSymbolAddress((void**)&rowptr, g_rowptr);
    cudaGetSymbolAddress((void**)&csr_src, g_csr_src);
    cudaGetSymbolAddress((void**)&S, g_S);
    cudaGetSymbolAddress((void**)&flag, g_scanflag);

    static bool attr_done = false;
    if (!attr_done) {
        cudaFuncSetAttribute(gat_fused, cudaFuncAttributeMaxDynamicSharedMemorySize,
                             (128 * 68 + 64 * 64) * 4);
        attr_done = true;
    }

    const int FB = (NN + 63) / 64;   // 1563 blocks

    // ---- CSR build + weight folding (8 launches total this call) ----
    zero_all<<<489, 256>>>((int4*)cnt, (float4*)S, flag);
    count_fold<<<782 + 132, 256>>>(dst, cnt, fw, Wn, We, bp, Wstk, avec);
    scan_lb<<<SCAN_NB, 256>>>(cnt, flag, rowptr);
    scatter_kernel<<<(EE / 4 + 255) / 256, 256>>>(src, dst, rowptr, cnt, csr_src, ea, S);

    // ---- 3 fused layers ----
    fused_layer<<<FB, 256>>>(x, csr_src, rowptr, S, Wn + 0 * 4096, We + 0 * 320,
                             bp + 0 * 64, h1, 0, 0, avec, nullptr, nullptr);
    fused_layer<<<FB, 256>>>(h1, csr_src, rowptr, S, Wn + 1 * 4096, We + 1 * 320,
                             bp + 1 * 64, h2, 1, 0, avec, nullptr, nullptr);
    fused_layer<<<FB, 256>>>(h2, csr_src, rowptr, S, Wn + 2 * 4096, We + 2 * 320,
                             bp + 2 * 64, h3, 1, 1, avec, asrc, adst);

    // ---- fused GAT tail (gather + projection + bias -> out) ----
    gat_fused<<<FB, 256, (128 * 68 + 64 * 64) * 4>>>(
        csr_src, rowptr, (const float2*)asrc, (const float2*)adst,
        h3, Wstk, b_gat, out);
}